// round 1
// baseline (speedup 1.0000x reference)
#include <cuda_runtime.h>
#include <cstdint>

#define CC    512
#define TLEN  1024
#define TT    32
#define NBLK  32
#define BATCH 32

// Scratch (no cudaMalloc allowed): transposed recurrent weight + spike-time exchange
__device__ float g_WT[CC * CC];
__device__ int   g_s1buf[2][BATCH][CC];

// ---------------------------------------------------------------------------
// Transpose rec_weight (W[i][j]) -> g_WT[j][i] so the gather is coalesced in i
// ---------------------------------------------------------------------------
__global__ void transpose_kernel(const float* __restrict__ W) {
    __shared__ float tile[32][33];
    int j0 = blockIdx.x * 32, i0 = blockIdx.y * 32;
    int tx = threadIdx.x, ty = threadIdx.y;
#pragma unroll
    for (int k = 0; k < 32; k += 8)
        tile[ty + k][tx] = W[(i0 + ty + k) * CC + (j0 + tx)];
    __syncthreads();
#pragma unroll
    for (int k = 0; k < 32; k += 8)
        g_WT[(j0 + ty + k) * CC + (i0 + tx)] = tile[tx][ty + k];
}

// ---------------------------------------------------------------------------
// Persistent SNN kernel: 1 thread = 1 (batch, channel); cluster(4 CTAs)=1 batch
// ---------------------------------------------------------------------------
__global__ void __cluster_dims__(4, 1, 1) __launch_bounds__(128)
snn_kernel(const float* __restrict__ x,
           const float* __restrict__ beta_raw,
           const float* __restrict__ p_raw,
           const float* __restrict__ b_raw,
           float* __restrict__ out)
{
    const int tid   = threadIdx.x;
    const int b     = blockIdx.x >> 2;
    const int ctile = blockIdx.x & 3;
    const int i     = ctile * 128 + tid;       // channel
    const int lane  = tid & 31, warp = tid >> 5;

    float beta = beta_raw[i];
    beta = fminf(fmaxf(beta, 0.001f), 0.999f);
    float p = fminf(fabsf(p_raw[i]), 0.999f);          // clip(|p|,0,0.999)
    float bb = fminf(fmaxf(fabsf(b_raw[i]), 0.001f), 1.0f);
    const float inv_p = 1.0f / p;

    // power tables, built like the reference (pow with float exponent)
    float bp[TT], pp[TT];
#pragma unroll
    for (int k = 0; k < TT; k++) {
        bp[k] = powf(beta, (float)k);          // beta^(t-s)
        pp[k] = powf(p, (float)(k + 1));       // p^(t+1)
    }

    __shared__ int s1_sm[CC];
    __shared__ __align__(16) unsigned masks[TT * 16];  // [t][round-of-32-channels]

    float mem_last = 0.0f, a_prev = 0.0f;
    int   s1_own = -1;

    const float* xrow = x   + (size_t)(b * CC + i) * TLEN;
    float*       orow = out + (size_t)(b * CC + i) * TLEN;

    for (int iter = 0; iter < NBLK; iter++) {
        float cur[TT];
        // ---- load x slice (8 x float4, 128B-aligned) ----
        const float4* xv = (const float4*)(xrow + iter * TT);
#pragma unroll
        for (int q = 0; q < 8; q++) {
            float4 v = xv[q];
            cur[q * 4 + 0] = v.x; cur[q * 4 + 1] = v.y;
            cur[q * 4 + 2] = v.z; cur[q * 4 + 3] = v.w;
        }

        float a_cur;
        if (iter > 0) {
            // ---- stage previous-block spike times for the whole batch ----
            const int pb = (iter - 1) & 1;
#pragma unroll
            for (int q = 0; q < 4; q++)
                s1_sm[tid + q * 128] = g_s1buf[pb][b][tid + q * 128];
            __syncthreads();

            // ---- deterministic bucket masks via ballots (warp w owns t in [8w,8w+8)) ----
            for (int r = 0; r < 16; r++) {
                int s = s1_sm[r * 32 + lane];
#pragma unroll
                for (int tt = 0; tt < 8; tt++) {
                    int t = warp * 8 + tt;
                    unsigned m = __ballot_sync(0xffffffffu, s == t);
                    if (lane == 0) masks[t * 16 + r] = m;
                }
            }
            __syncthreads();

            // ---- recurrent gather: cur[t] += sum_{j spiked at t} WT[j][i] ----
#pragma unroll
            for (int t = 0; t < TT; t++) {
                float acc = 0.0f;
                const uint4* mp = (const uint4*)(&masks[t * 16]);
#pragma unroll
                for (int rq = 0; rq < 4; rq++) {
                    uint4 mv = mp[rq];
                    unsigned mm[4] = { mv.x, mv.y, mv.z, mv.w };
#pragma unroll
                    for (int u = 0; u < 4; u++) {
                        unsigned m = mm[u];
                        const int base = (rq * 4 + u) * 32;
                        while (m) {                      // uniform across warp
                            int j = base + __ffs(m) - 1;
                            m &= m - 1;
                            acc += g_WT[j * CC + i];     // coalesced in i
                        }
                    }
                }
                cur[t] += acc;
            }

            // ---- mask / zeroing / v_init / adaptation update ----
            if (s1_own >= 0) {
#pragma unroll
                for (int t = 0; t < TT; t++)
                    if (t < s1_own) cur[t] = 0.0f;       // zero before prev spike
            }
            float v_init = (s1_own >= 0) ? 0.0f : mem_last;
            float a_at   = powf(p, (float)(s1_own + 1)) * a_prev + inv_p;
            float new_a  = a_at * powf(p, (float)(TT - 1 - s1_own));
            a_cur  = (s1_own >= 0) ? new_a : pp[TT - 1] * a_prev;
            a_prev = a_cur;
            cur[0] += beta * v_init;
        } else {
            a_cur = 0.0f;      // a_kernel0 = 0  ->  v_th = 1 exactly
        }

        // ---- membrane (dot form, ascending s like reference K@cur) + first crossing ----
        int s1_new = -1;
        float m_last = 0.0f;
#pragma unroll
        for (int t = 0; t < TT; t++) {
            float m = 0.0f;
#pragma unroll
            for (int s = 0; s <= t; s++)
                m = fmaf(bp[t - s], cur[s], m);
            float vth = 1.0f + bb * (pp[t] * a_cur);
            if (((m - vth) > 0.0f) && s1_new < 0) s1_new = t;
            m_last = m;
        }
        mem_last = m_last;
        s1_own   = s1_new;

        // ---- write spikes (z==1 <=> t == first crossing) ----
        float4* ov = (float4*)(orow + iter * TT);
#pragma unroll
        for (int q = 0; q < 8; q++) {
            float4 v;
            v.x = (q * 4 + 0 == s1_new) ? 1.0f : 0.0f;
            v.y = (q * 4 + 1 == s1_new) ? 1.0f : 0.0f;
            v.z = (q * 4 + 2 == s1_new) ? 1.0f : 0.0f;
            v.w = (q * 4 + 3 == s1_new) ? 1.0f : 0.0f;
            ov[q] = v;
        }
        g_s1buf[iter & 1][b][i] = s1_new;

        // ---- publish + batch-scope sync (cluster = this batch) ----
        if (iter < NBLK - 1) {
            asm volatile("fence.acq_rel.cluster;" ::: "memory");
            asm volatile("barrier.cluster.arrive.aligned;" ::: "memory");
            asm volatile("barrier.cluster.wait.aligned;" ::: "memory");
        }
    }
}

// ---------------------------------------------------------------------------
extern "C" void kernel_launch(void* const* d_in, const int* in_sizes, int n_in,
                              void* d_out, int out_size)
{
    const float* x        = (const float*)d_in[0];
    const float* beta_raw = (const float*)d_in[1];
    const float* rec_w    = (const float*)d_in[2];
    const float* p_raw    = (const float*)d_in[3];
    const float* b_raw    = (const float*)d_in[4];
    float* out = (float*)d_out;

    transpose_kernel<<<dim3(16, 16), dim3(32, 8)>>>(rec_w);
    snn_kernel<<<128, 128>>>(x, beta_raw, p_raw, b_raw, out);
}

// round 2
// speedup vs baseline: 2.3922x; 2.3922x over previous
#include <cuda_runtime.h>
#include <cstdint>

#define CC    512
#define TLEN  1024
#define TT    32
#define NBLK  32
#define BATCH 32

// Scratch (no cudaMalloc allowed): transposed recurrent weight + spike-time exchange
__device__ float g_WT[CC * CC];
__device__ int   g_s1buf[2][BATCH][CC];

// ---------------------------------------------------------------------------
// Transpose rec_weight (W[i][j]) -> g_WT[j][i] so the gather is coalesced in i
// ---------------------------------------------------------------------------
__global__ void transpose_kernel(const float* __restrict__ W) {
    __shared__ float tile[32][33];
    int j0 = blockIdx.x * 32, i0 = blockIdx.y * 32;
    int tx = threadIdx.x, ty = threadIdx.y;
#pragma unroll
    for (int k = 0; k < 32; k += 8)
        tile[ty + k][tx] = W[(i0 + ty + k) * CC + (j0 + tx)];
    __syncthreads();
#pragma unroll
    for (int k = 0; k < 32; k += 8)
        g_WT[(j0 + ty + k) * CC + (i0 + tx)] = tile[tx][ty + k];
}

// ---------------------------------------------------------------------------
// Persistent SNN kernel: 1 thread = 1 (batch, channel); cluster(4 CTAs)=1 batch
// Gather restructured: compacted per-t lists in smem + paired unroll-8 loads
// (exact ascending-j per-t add order preserved -> bitwise-identical spikes).
// ---------------------------------------------------------------------------
__global__ void __cluster_dims__(4, 1, 1) __launch_bounds__(128)
snn_kernel(const float* __restrict__ x,
           const float* __restrict__ beta_raw,
           const float* __restrict__ p_raw,
           const float* __restrict__ b_raw,
           float* __restrict__ out)
{
    const int tid   = threadIdx.x;
    const int b     = blockIdx.x >> 2;
    if (b >= BATCH) return;                    // dummy padding clusters exit whole
    const int ctile = blockIdx.x & 3;
    const int i     = ctile * 128 + tid;       // channel
    const int lane  = tid & 31, warp = tid >> 5;

    float beta = beta_raw[i];
    beta = fminf(fmaxf(beta, 0.001f), 0.999f);
    float p = fminf(fabsf(p_raw[i]), 0.999f);
    float bb = fminf(fmaxf(fabsf(b_raw[i]), 0.001f), 1.0f);
    const float inv_p = 1.0f / p;

    // power tables, built exactly like round-1 (powf with float exponent)
    float bp[TT], pp[TT];
#pragma unroll
    for (int k = 0; k < TT; k++) {
        bp[k] = powf(beta, (float)k);          // beta^(t-s)
        pp[k] = powf(p, (float)(k + 1));       // p^(t+1)
    }

    __shared__ int       s1_sm[CC];
    __shared__ unsigned  masks[TT][16];        // [t][round-of-32-channels]
    __shared__ int       off_sm[TT + 1];       // exclusive offsets per t
    __shared__ short     lst[CC];              // compacted j list, grouped by t, asc j

    float mem_last = 0.0f, a_prev = 0.0f;
    int   s1_own = -1;

    const float* xrow = x   + (size_t)(b * CC + i) * TLEN;
    float*       orow = out + (size_t)(b * CC + i) * TLEN;
    const float* WTi  = g_WT + i;

    // preload x block 0
    float xb[TT];
    {
        const float4* xv = (const float4*)(xrow);
#pragma unroll
        for (int q = 0; q < 8; q++) {
            float4 v = xv[q];
            xb[q * 4 + 0] = v.x; xb[q * 4 + 1] = v.y;
            xb[q * 4 + 2] = v.z; xb[q * 4 + 3] = v.w;
        }
    }

    for (int iter = 0; iter < NBLK; iter++) {
        float cur[TT];
#pragma unroll
        for (int t = 0; t < TT; t++) cur[t] = xb[t];

        float a_cur;
        if (iter > 0) {
            // ---- stage previous-block spike times for the whole batch ----
            const int pb = (iter - 1) & 1;
#pragma unroll
            for (int q = 0; q < 4; q++)
                s1_sm[tid + q * 128] = g_s1buf[pb][b][tid + q * 128];
            __syncthreads();

            // ---- deterministic bucket masks via ballots (warp w owns rounds w,w+4,w+8,w+12)
#pragma unroll
            for (int rr = 0; rr < 4; rr++) {
                int r = warp + rr * 4;
                int s = s1_sm[r * 32 + lane];
#pragma unroll
                for (int t = 0; t < TT; t++) {
                    unsigned m = __ballot_sync(0xffffffffu, s == t);
                    if (lane == 0) masks[t][r] = m;
                }
            }
            __syncthreads();

            // ---- warp 0: counts, exclusive scan, compacted list (asc r, asc bit => asc j)
            if (warp == 0) {
                int cnt = 0;
#pragma unroll
                for (int r = 0; r < 16; r++) cnt += __popc(masks[lane][r]);
                int sc = cnt;
#pragma unroll
                for (int d = 1; d < 32; d <<= 1) {
                    int o = __shfl_up_sync(0xffffffffu, sc, d);
                    if (lane >= d) sc += o;
                }
                int excl = sc - cnt;
                off_sm[lane] = excl;
                if (lane == 31) off_sm[32] = sc;
                int pos = excl;
#pragma unroll
                for (int r = 0; r < 16; r++) {
                    unsigned m = masks[lane][r];
                    while (m) {
                        int j = r * 32 + __ffs(m) - 1;
                        m &= m - 1;
                        lst[pos++] = (short)j;
                    }
                }
            }
            __syncthreads();

            // ---- recurrent gather: cur[t] += sum_{j spiked at t, asc j} WT[j][i]
            // paired groups (t, t+16) for MLP=16; add order within group exact.
#pragma unroll
            for (int th = 0; th < 16; th++) {
                const int tA = th, tB = th + 16;
                int kA = off_sm[tA], eA = off_sm[tA + 1];
                int kB = off_sm[tB], eB = off_sm[tB + 1];
                float aA = 0.0f, aB = 0.0f;
#pragma unroll 1
                while ((kA + 8 <= eA) && (kB + 8 <= eB)) {
                    float wa[8], wb[8];
#pragma unroll
                    for (int u = 0; u < 8; u++) wa[u] = WTi[(int)lst[kA + u] * CC];
#pragma unroll
                    for (int u = 0; u < 8; u++) wb[u] = WTi[(int)lst[kB + u] * CC];
#pragma unroll
                    for (int u = 0; u < 8; u++) aA += wa[u];
#pragma unroll
                    for (int u = 0; u < 8; u++) aB += wb[u];
                    kA += 8; kB += 8;
                }
#pragma unroll 1
                while (kA + 8 <= eA) {
                    float wa[8];
#pragma unroll
                    for (int u = 0; u < 8; u++) wa[u] = WTi[(int)lst[kA + u] * CC];
#pragma unroll
                    for (int u = 0; u < 8; u++) aA += wa[u];
                    kA += 8;
                }
#pragma unroll 1
                while (kB + 8 <= eB) {
                    float wb[8];
#pragma unroll
                    for (int u = 0; u < 8; u++) wb[u] = WTi[(int)lst[kB + u] * CC];
#pragma unroll
                    for (int u = 0; u < 8; u++) aB += wb[u];
                    kB += 8;
                }
#pragma unroll 1
                for (; kA < eA; kA++) aA += WTi[(int)lst[kA] * CC];
#pragma unroll 1
                for (; kB < eB; kB++) aB += WTi[(int)lst[kB] * CC];
                cur[tA] += aA;
                cur[tB] += aB;
            }

            // ---- mask / zeroing / v_init / adaptation update (identical to R1) ----
            if (s1_own >= 0) {
#pragma unroll
                for (int t = 0; t < TT; t++)
                    if (t < s1_own) cur[t] = 0.0f;
            }
            float v_init = (s1_own >= 0) ? 0.0f : mem_last;
            float a_at   = powf(p, (float)(s1_own + 1)) * a_prev + inv_p;
            float new_a  = a_at * powf(p, (float)(TT - 1 - s1_own));
            a_cur  = (s1_own >= 0) ? new_a : pp[TT - 1] * a_prev;
            a_prev = a_cur;
            cur[0] += beta * v_init;
        } else {
            a_cur = 0.0f;      // a_kernel0 = 0  ->  v_th = 1 exactly
        }

        // ---- membrane (dot form, ascending s) + first crossing (identical to R1) ----
        int s1_new = -1;
        float m_last = 0.0f;
#pragma unroll
        for (int t = 0; t < TT; t++) {
            float m = 0.0f;
#pragma unroll
            for (int s = 0; s <= t; s++)
                m = fmaf(bp[t - s], cur[s], m);
            float vth = 1.0f + bb * (pp[t] * a_cur);
            if (((m - vth) > 0.0f) && s1_new < 0) s1_new = t;
            m_last = m;
        }
        mem_last = m_last;
        s1_own   = s1_new;

        // ---- write spikes (z==1 <=> t == first crossing) ----
        float4* ov = (float4*)(orow + iter * TT);
#pragma unroll
        for (int q = 0; q < 8; q++) {
            float4 v;
            v.x = (q * 4 + 0 == s1_new) ? 1.0f : 0.0f;
            v.y = (q * 4 + 1 == s1_new) ? 1.0f : 0.0f;
            v.z = (q * 4 + 2 == s1_new) ? 1.0f : 0.0f;
            v.w = (q * 4 + 3 == s1_new) ? 1.0f : 0.0f;
            ov[q] = v;
        }
        g_s1buf[iter & 1][b][i] = s1_new;

        // ---- prefetch next x block, then publish + batch-scope sync ----
        if (iter < NBLK - 1) {
            const float4* xv = (const float4*)(xrow + (iter + 1) * TT);
#pragma unroll
            for (int q = 0; q < 8; q++) {
                float4 v = xv[q];
                xb[q * 4 + 0] = v.x; xb[q * 4 + 1] = v.y;
                xb[q * 4 + 2] = v.z; xb[q * 4 + 3] = v.w;
            }
            asm volatile("fence.acq_rel.cluster;" ::: "memory");
            asm volatile("barrier.cluster.arrive.aligned;" ::: "memory");
            asm volatile("barrier.cluster.wait.aligned;" ::: "memory");
        }
    }
}

// ---------------------------------------------------------------------------
extern "C" void kernel_launch(void* const* d_in, const int* in_sizes, int n_in,
                              void* d_out, int out_size)
{
    const float* x        = (const float*)d_in[0];
    const float* beta_raw = (const float*)d_in[1];
    const float* rec_w    = (const float*)d_in[2];
    const float* p_raw    = (const float*)d_in[3];
    const float* b_raw    = (const float*)d_in[4];
    float* out = (float*)d_out;

    transpose_kernel<<<dim3(16, 16), dim3(32, 8)>>>(rec_w);
    // grid padded to 152 (>=148 SMs): dummy clusters (b>=32) exit immediately
    snn_kernel<<<152, 128>>>(x, beta_raw, p_raw, b_raw, out);
}

// round 3
// speedup vs baseline: 5.3242x; 2.2256x over previous
#include <cuda_runtime.h>
#include <cstdint>

#define CC    512
#define TLEN  1024
#define TT    32
#define NBLK  32
#define BATCH 32

// Scratch (no cudaMalloc allowed): transposed recurrent weight + spike-time exchange
__device__ float g_WT[CC * CC];
__device__ int   g_s1buf[2][BATCH][CC];

// ---------------------------------------------------------------------------
// Transpose rec_weight (W[i][j]) -> g_WT[j][i] so the gather is coalesced in i
// ---------------------------------------------------------------------------
__global__ void transpose_kernel(const float* __restrict__ W) {
    __shared__ float tile[32][33];
    int j0 = blockIdx.x * 32, i0 = blockIdx.y * 32;
    int tx = threadIdx.x, ty = threadIdx.y;
#pragma unroll
    for (int k = 0; k < 32; k += 8)
        tile[ty + k][tx] = W[(i0 + ty + k) * CC + (j0 + tx)];
    __syncthreads();
#pragma unroll
    for (int k = 0; k < 32; k += 8)
        g_WT[(j0 + ty + k) * CC + (i0 + tx)] = tile[tx][ty + k];
}

// ---------------------------------------------------------------------------
// R3: thread = (channel, t-group of 8). 512-thread CTA, cluster(4) = 1 batch.
// TG is a template parameter so every t index is compile-time (no spills).
// Exact arithmetic order preserved everywhere -> bitwise-identical spikes.
// ---------------------------------------------------------------------------
template<int TG>
__device__ __forceinline__ void run_loop(
    int cl, int lane, int warp, int b, int i,
    const float* __restrict__ xrow, float* __restrict__ orow,
    const float* __restrict__ WTi,
    float beta, float p, float bb, float inv_p,
    int*       s1_sm,           // [512]
    unsigned  (*masks)[16],     // [32][16]
    int*       off_sm,          // [33]
    short*     lst,             // [512]
    float     (*cur_sm)[33],    // [128][33]
    int       (*cand_sm)[128],  // [4][128]
    float*     memlast_sm)      // [128]
{
    constexpr int BASE = TG * 8;

    // power tables, built exactly like R1/R2 (powf with float exponent)
    float bp[BASE + 8];
#pragma unroll
    for (int k = 0; k < BASE + 8; k++) bp[k] = powf(beta, (float)k);
    float ppo[8];
#pragma unroll
    for (int u = 0; u < 8; u++) ppo[u] = powf(p, (float)(BASE + u + 1));
    const float pp31 = powf(p, (float)TT);   // p^(TT-1+1), as in R2 pp[TT-1]

    float mem_last = 0.0f, a_prev = 0.0f;
    int   s1_own = -1;

    float* crow = cur_sm[cl];

    for (int iter = 0; iter < NBLK; iter++) {
        // ---- load own 8 x values (2 x float4, 32B) ----
        float cur[8];
        {
            const float4* xv = (const float4*)(xrow + iter * TT + BASE);
            float4 v0 = xv[0], v1 = xv[1];
            cur[0] = v0.x; cur[1] = v0.y; cur[2] = v0.z; cur[3] = v0.w;
            cur[4] = v1.x; cur[5] = v1.y; cur[6] = v1.z; cur[7] = v1.w;
        }

        float a_cur;
        if (iter > 0) {
            // ---- stage previous-block spike times (whole batch, 1/thread) ----
            const int pb = (iter - 1) & 1;
            const int tid = TG * 128 + cl;
            s1_sm[tid] = g_s1buf[pb][b][tid];
            __syncthreads();

            // ---- deterministic bucket masks via ballots: warp w owns round w ----
            {
                int s = s1_sm[warp * 32 + lane];
#pragma unroll
                for (int t = 0; t < TT; t++) {
                    unsigned m = __ballot_sync(0xffffffffu, s == t);
                    if (lane == 0) masks[t][warp] = m;
                }
            }
            __syncthreads();

            // ---- warp 0: counts, scan, compacted list (asc r, asc bit => asc j) ----
            if (TG == 0 && warp == 0) {
                int cnt = 0;
#pragma unroll
                for (int r = 0; r < 16; r++) cnt += __popc(masks[lane][r]);
                int sc = cnt;
#pragma unroll
                for (int d = 1; d < 32; d <<= 1) {
                    int o = __shfl_up_sync(0xffffffffu, sc, d);
                    if (lane >= d) sc += o;
                }
                int excl = sc - cnt;
                off_sm[lane] = excl;
                if (lane == 31) off_sm[32] = sc;
                int pos = excl;
#pragma unroll
                for (int r = 0; r < 16; r++) {
                    unsigned m = masks[lane][r];
                    while (m) {
                        int j = r * 32 + __ffs(m) - 1;
                        m &= m - 1;
                        lst[pos++] = (short)j;
                    }
                }
            }
            __syncthreads();

            // ---- recurrent gather: own 8 buckets as 4 pairs (tA=BASE+u, tB=BASE+u+4) ----
#pragma unroll
            for (int u = 0; u < 4; u++) {
                const int tA = BASE + u, tB = BASE + u + 4;
                int kA = off_sm[tA], eA = off_sm[tA + 1];
                int kB = off_sm[tB], eB = off_sm[tB + 1];
                float aA = 0.0f, aB = 0.0f;
#pragma unroll 1
                while ((kA + 8 <= eA) && (kB + 8 <= eB)) {
                    float wa[8], wb[8];
#pragma unroll
                    for (int v = 0; v < 8; v++) wa[v] = WTi[(int)lst[kA + v] * CC];
#pragma unroll
                    for (int v = 0; v < 8; v++) wb[v] = WTi[(int)lst[kB + v] * CC];
#pragma unroll
                    for (int v = 0; v < 8; v++) aA += wa[v];
#pragma unroll
                    for (int v = 0; v < 8; v++) aB += wb[v];
                    kA += 8; kB += 8;
                }
#pragma unroll 1
                while (kA + 8 <= eA) {
                    float wa[8];
#pragma unroll
                    for (int v = 0; v < 8; v++) wa[v] = WTi[(int)lst[kA + v] * CC];
#pragma unroll
                    for (int v = 0; v < 8; v++) aA += wa[v];
                    kA += 8;
                }
#pragma unroll 1
                while (kB + 8 <= eB) {
                    float wb[8];
#pragma unroll
                    for (int v = 0; v < 8; v++) wb[v] = WTi[(int)lst[kB + v] * CC];
#pragma unroll
                    for (int v = 0; v < 8; v++) aB += wb[v];
                    kB += 8;
                }
#pragma unroll 1
                for (; kA < eA; kA++) aA += WTi[(int)lst[kA] * CC];
#pragma unroll 1
                for (; kB < eB; kB++) aB += WTi[(int)lst[kB] * CC];
                cur[u]     += aA;
                cur[u + 4] += aB;
            }

            // ---- zeroing / v_init / adaptation (replicated per channel) ----
            if (s1_own >= 0) {
#pragma unroll
                for (int u = 0; u < 8; u++)
                    if (BASE + u < s1_own) cur[u] = 0.0f;
            }
            float v_init = (s1_own >= 0) ? 0.0f : mem_last;
            float a_at   = powf(p, (float)(s1_own + 1)) * a_prev + inv_p;
            float new_a  = a_at * powf(p, (float)(TT - 1 - s1_own));
            a_cur  = (s1_own >= 0) ? new_a : pp31 * a_prev;
            a_prev = a_cur;
            if (TG == 0) cur[0] += beta * v_init;
        } else {
            a_cur = 0.0f;      // a_kernel0 = 0 -> v_th = 1 exactly
        }

        // ---- publish cur to smem tile (padded, conflict-free) ----
#pragma unroll
        for (int u = 0; u < 8; u++) crow[BASE + u] = cur[u];
        __syncthreads();

        // ---- membrane (exact ascending-s fmaf chain) + first crossing ----
        int   cand = 64;
        float m_last = 0.0f;
#pragma unroll
        for (int u = 0; u < 8; u++) {
            const int t = BASE + u;
            float m = 0.0f;
#pragma unroll
            for (int s = 0; s <= t; s++)
                m = fmaf(bp[t - s], crow[s], m);
            float vth = 1.0f + bb * (ppo[u] * a_cur);
            if (((m - vth) > 0.0f) && cand == 64) cand = t;
            if (TG == 3 && u == 7) m_last = m;
        }
        cand_sm[TG][cl] = cand;
        if (TG == 3) memlast_sm[cl] = m_last;
        __syncthreads();

        // ---- combine: first crossing over all 4 t-groups; mem[31] broadcast ----
        int s1n = min(min(cand_sm[0][cl], cand_sm[1][cl]),
                      min(cand_sm[2][cl], cand_sm[3][cl]));
        int s1_new = (s1n == 64) ? -1 : s1n;
        mem_last = memlast_sm[cl];
        s1_own   = s1_new;

        // ---- write own 8 spikes ----
        {
            float4* ov = (float4*)(orow + iter * TT + BASE);
            float4 v0, v1;
            v0.x = (BASE + 0 == s1_new) ? 1.0f : 0.0f;
            v0.y = (BASE + 1 == s1_new) ? 1.0f : 0.0f;
            v0.z = (BASE + 2 == s1_new) ? 1.0f : 0.0f;
            v0.w = (BASE + 3 == s1_new) ? 1.0f : 0.0f;
            v1.x = (BASE + 4 == s1_new) ? 1.0f : 0.0f;
            v1.y = (BASE + 5 == s1_new) ? 1.0f : 0.0f;
            v1.z = (BASE + 6 == s1_new) ? 1.0f : 0.0f;
            v1.w = (BASE + 7 == s1_new) ? 1.0f : 0.0f;
            ov[0] = v0; ov[1] = v1;
        }
        if (TG == 0) g_s1buf[iter & 1][b][i] = s1_new;

        // ---- publish + batch-scope sync (cluster = this batch) ----
        if (iter < NBLK - 1) {
            asm volatile("fence.acq_rel.cluster;" ::: "memory");
            asm volatile("barrier.cluster.arrive.aligned;" ::: "memory");
            asm volatile("barrier.cluster.wait.aligned;" ::: "memory");
        }
    }
}

__global__ void __cluster_dims__(4, 1, 1) __launch_bounds__(512, 1)
snn_kernel(const float* __restrict__ x,
           const float* __restrict__ beta_raw,
           const float* __restrict__ p_raw,
           const float* __restrict__ b_raw,
           float* __restrict__ out)
{
    const int tid  = threadIdx.x;
    const int b    = blockIdx.x >> 2;
    if (b >= BATCH) return;                 // padding clusters exit whole
    const int ctile = blockIdx.x & 3;
    const int cl   = tid & 127;             // channel-local
    const int tg   = tid >> 7;              // t-group (0..3)
    const int lane = tid & 31, warp = tid >> 5;
    const int i    = ctile * 128 + cl;      // channel

    float beta = beta_raw[i];
    beta = fminf(fmaxf(beta, 0.001f), 0.999f);
    float p  = fminf(fabsf(p_raw[i]), 0.999f);
    float bb = fminf(fmaxf(fabsf(b_raw[i]), 0.001f), 1.0f);
    const float inv_p = 1.0f / p;

    __shared__ int       s1_sm[CC];
    __shared__ unsigned  masks[TT][16];
    __shared__ int       off_sm[TT + 1];
    __shared__ short     lst[CC];
    __shared__ float     cur_sm[128][33];
    __shared__ int       cand_sm[4][128];
    __shared__ float     memlast_sm[128];

    const float* xrow = x   + (size_t)(b * CC + i) * TLEN;
    float*       orow = out + (size_t)(b * CC + i) * TLEN;
    const float* WTi  = g_WT + i;

    switch (tg) {
    case 0: run_loop<0>(cl, lane, warp, b, i, xrow, orow, WTi, beta, p, bb, inv_p,
                        s1_sm, masks, off_sm, lst, cur_sm, cand_sm, memlast_sm); break;
    case 1: run_loop<1>(cl, lane, warp, b, i, xrow, orow, WTi, beta, p, bb, inv_p,
                        s1_sm, masks, off_sm, lst, cur_sm, cand_sm, memlast_sm); break;
    case 2: run_loop<2>(cl, lane, warp, b, i, xrow, orow, WTi, beta, p, bb, inv_p,
                        s1_sm, masks, off_sm, lst, cur_sm, cand_sm, memlast_sm); break;
    default: run_loop<3>(cl, lane, warp, b, i, xrow, orow, WTi, beta, p, bb, inv_p,
                        s1_sm, masks, off_sm, lst, cur_sm, cand_sm, memlast_sm); break;
    }
}

// ---------------------------------------------------------------------------
extern "C" void kernel_launch(void* const* d_in, const int* in_sizes, int n_in,
                              void* d_out, int out_size)
{
    const float* x        = (const float*)d_in[0];
    const float* beta_raw = (const float*)d_in[1];
    const float* rec_w    = (const float*)d_in[2];
    const float* p_raw    = (const float*)d_in[3];
    const float* b_raw    = (const float*)d_in[4];
    float* out = (float*)d_out;

    transpose_kernel<<<dim3(16, 16), dim3(32, 8)>>>(rec_w);
    // 148 CTAs (37 clusters of 4): clusters with b>=32 exit immediately
    snn_kernel<<<148, 512>>>(x, beta_raw, p_raw, b_raw, out);
}

// round 4
// speedup vs baseline: 6.5061x; 1.2220x over previous
#include <cuda_runtime.h>
#include <cstdint>

#define CC    512
#define TLEN  1024
#define TT    32
#define NBLK  32
#define BATCH 32

// Scratch (no cudaMalloc allowed): transposed recurrent weight + spike-time exchange
__device__ float g_WT[CC * CC];
__device__ int   g_s1buf[2][BATCH][CC];

// ---------------------------------------------------------------------------
// Transpose rec_weight (W[i][j]) -> g_WT[j][i] so the gather is coalesced in i
// ---------------------------------------------------------------------------
__global__ void transpose_kernel(const float* __restrict__ W) {
    __shared__ float tile[32][33];
    int j0 = blockIdx.x * 32, i0 = blockIdx.y * 32;
    int tx = threadIdx.x, ty = threadIdx.y;
#pragma unroll
    for (int k = 0; k < 32; k += 8)
        tile[ty + k][tx] = W[(i0 + ty + k) * CC + (j0 + tx)];
    __syncthreads();
#pragma unroll
    for (int k = 0; k < 32; k += 8)
        g_WT[(j0 + ty + k) * CC + (i0 + tx)] = tile[tx][ty + k];
}

// ---------------------------------------------------------------------------
// R4: thread = (channel, t-group of 4). 1024-thread CTA, cluster(4) = 1 batch.
// occ 50% (32 warps/SM). Exact arithmetic order preserved -> bitwise spikes.
// ---------------------------------------------------------------------------
template<int TG>
__device__ __forceinline__ void run_loop(
    int cl, int lane, int warp, int b, int i,
    const float* __restrict__ xrow, float* __restrict__ orow,
    const float* __restrict__ WTi,
    float beta, float p, float bb, float inv_p,
    int*       s1_sm,           // [512]
    unsigned  (*masks)[16],     // [32][16]
    int*       off_sm,          // [33]
    short*     lst,             // [512]
    float     (*cur_sm)[33],    // [128][33]
    int       (*cand_sm)[128],  // [8][128]
    float*     memlast_sm)      // [128]
{
    constexpr int BASE = TG * 4;

    // power tables, built exactly like R1-R3 (powf with float exponent)
    float bp[BASE + 4];
#pragma unroll
    for (int k = 0; k < BASE + 4; k++) bp[k] = powf(beta, (float)k);
    float ppo[4];
#pragma unroll
    for (int u = 0; u < 4; u++) ppo[u] = powf(p, (float)(BASE + u + 1));
    const float pp31 = powf(p, (float)TT);   // p^32, as in R2/R3

    float mem_last = 0.0f, a_prev = 0.0f;
    int   s1_own = -1;

    float* crow = cur_sm[cl];
    const int tid = TG * 128 + cl;

    for (int iter = 0; iter < NBLK; iter++) {
        // ---- load own 4 x values (1 x float4, 16B) ----
        float cur[4];
        {
            const float4 v = *(const float4*)(xrow + iter * TT + BASE);
            cur[0] = v.x; cur[1] = v.y; cur[2] = v.z; cur[3] = v.w;
        }

        float a_cur;
        if (iter > 0) {
            // ---- stage previous-block spike times (whole batch) ----
            const int pb = (iter - 1) & 1;
            if (TG < 4) s1_sm[tid] = g_s1buf[pb][b][tid];
            __syncthreads();

            // ---- deterministic bucket masks via ballots: warps 0..15 own rounds ----
            if (warp < 16) {
                int s = s1_sm[warp * 32 + lane];
#pragma unroll
                for (int t = 0; t < TT; t++) {
                    unsigned m = __ballot_sync(0xffffffffu, s == t);
                    if (lane == 0) masks[t][warp] = m;
                }
            }
            __syncthreads();

            // ---- warp 0: counts, scan, compacted list (asc r, asc bit => asc j) ----
            if (TG == 0 && warp == 0) {
                int cnt = 0;
#pragma unroll
                for (int r = 0; r < 16; r++) cnt += __popc(masks[lane][r]);
                int sc = cnt;
#pragma unroll
                for (int d = 1; d < 32; d <<= 1) {
                    int o = __shfl_up_sync(0xffffffffu, sc, d);
                    if (lane >= d) sc += o;
                }
                int excl = sc - cnt;
                off_sm[lane] = excl;
                if (lane == 31) off_sm[32] = sc;
                int pos = excl;
#pragma unroll
                for (int r = 0; r < 16; r++) {
                    unsigned m = masks[lane][r];
                    while (m) {
                        int j = r * 32 + __ffs(m) - 1;
                        m &= m - 1;
                        lst[pos++] = (short)j;
                    }
                }
            }
            __syncthreads();

            // ---- recurrent gather: own 4 buckets as 2 pairs; asc-j order exact ----
#pragma unroll
            for (int u = 0; u < 2; u++) {
                const int tA = BASE + u, tB = BASE + u + 2;
                int kA = off_sm[tA], eA = off_sm[tA + 1];
                int kB = off_sm[tB], eB = off_sm[tB + 1];
                float aA = 0.0f, aB = 0.0f;
#pragma unroll 1
                while ((kA + 8 <= eA) && (kB + 8 <= eB)) {
                    float wa[8], wb[8];
#pragma unroll
                    for (int v = 0; v < 8; v++) wa[v] = WTi[(int)lst[kA + v] * CC];
#pragma unroll
                    for (int v = 0; v < 8; v++) wb[v] = WTi[(int)lst[kB + v] * CC];
#pragma unroll
                    for (int v = 0; v < 8; v++) aA += wa[v];
#pragma unroll
                    for (int v = 0; v < 8; v++) aB += wb[v];
                    kA += 8; kB += 8;
                }
#pragma unroll 1
                while (kA + 8 <= eA) {
                    float wa[8];
#pragma unroll
                    for (int v = 0; v < 8; v++) wa[v] = WTi[(int)lst[kA + v] * CC];
#pragma unroll
                    for (int v = 0; v < 8; v++) aA += wa[v];
                    kA += 8;
                }
#pragma unroll 1
                while (kB + 8 <= eB) {
                    float wb[8];
#pragma unroll
                    for (int v = 0; v < 8; v++) wb[v] = WTi[(int)lst[kB + v] * CC];
#pragma unroll
                    for (int v = 0; v < 8; v++) aB += wb[v];
                    kB += 8;
                }
#pragma unroll 1
                for (; kA < eA; kA++) aA += WTi[(int)lst[kA] * CC];
#pragma unroll 1
                for (; kB < eB; kB++) aB += WTi[(int)lst[kB] * CC];
                cur[u]     += aA;
                cur[u + 2] += aB;
            }

            // ---- zeroing / v_init / adaptation (replicated per channel) ----
            if (s1_own >= 0) {
#pragma unroll
                for (int u = 0; u < 4; u++)
                    if (BASE + u < s1_own) cur[u] = 0.0f;
            }
            float v_init = (s1_own >= 0) ? 0.0f : mem_last;
            float a_at   = powf(p, (float)(s1_own + 1)) * a_prev + inv_p;
            float new_a  = a_at * powf(p, (float)(TT - 1 - s1_own));
            a_cur  = (s1_own >= 0) ? new_a : pp31 * a_prev;
            a_prev = a_cur;
            if (TG == 0) cur[0] += beta * v_init;
        } else {
            a_cur = 0.0f;      // a_kernel0 = 0 -> v_th = 1 exactly
        }

        // ---- publish cur to smem tile (padded, conflict-free) ----
#pragma unroll
        for (int u = 0; u < 4; u++) crow[BASE + u] = cur[u];
        __syncthreads();

        // ---- membrane (exact ascending-s fmaf chain) + first crossing ----
        int   cand = 64;
        float m_last = 0.0f;
#pragma unroll
        for (int u = 0; u < 4; u++) {
            const int t = BASE + u;
            float m = 0.0f;
#pragma unroll
            for (int s = 0; s <= t; s++)
                m = fmaf(bp[t - s], crow[s], m);
            float vth = 1.0f + bb * (ppo[u] * a_cur);
            if (((m - vth) > 0.0f) && cand == 64) cand = t;
            if (TG == 7 && u == 3) m_last = m;
        }
        cand_sm[TG][cl] = cand;
        if (TG == 7) memlast_sm[cl] = m_last;
        __syncthreads();

        // ---- combine: first crossing over all 8 t-groups; mem[31] broadcast ----
        int s1n = min(min(min(cand_sm[0][cl], cand_sm[1][cl]),
                          min(cand_sm[2][cl], cand_sm[3][cl])),
                      min(min(cand_sm[4][cl], cand_sm[5][cl]),
                          min(cand_sm[6][cl], cand_sm[7][cl])));
        int s1_new = (s1n == 64) ? -1 : s1n;
        mem_last = memlast_sm[cl];
        s1_own   = s1_new;

        // ---- write own 4 spikes ----
        {
            float4 v;
            v.x = (BASE + 0 == s1_new) ? 1.0f : 0.0f;
            v.y = (BASE + 1 == s1_new) ? 1.0f : 0.0f;
            v.z = (BASE + 2 == s1_new) ? 1.0f : 0.0f;
            v.w = (BASE + 3 == s1_new) ? 1.0f : 0.0f;
            *(float4*)(orow + iter * TT + BASE) = v;
        }
        if (TG == 0) g_s1buf[iter & 1][b][i] = s1_new;

        // ---- publish + batch-scope sync (cluster = this batch) ----
        if (iter < NBLK - 1) {
            asm volatile("fence.acq_rel.cluster;" ::: "memory");
            asm volatile("barrier.cluster.arrive.aligned;" ::: "memory");
            asm volatile("barrier.cluster.wait.aligned;" ::: "memory");
        }
    }
}

__global__ void __cluster_dims__(4, 1, 1) __launch_bounds__(1024, 1)
snn_kernel(const float* __restrict__ x,
           const float* __restrict__ beta_raw,
           const float* __restrict__ p_raw,
           const float* __restrict__ b_raw,
           float* __restrict__ out)
{
    const int tid  = threadIdx.x;
    const int b    = blockIdx.x >> 2;
    if (b >= BATCH) return;                 // padding clusters exit whole
    const int ctile = blockIdx.x & 3;
    const int cl   = tid & 127;             // channel-local
    const int tg   = tid >> 7;              // t-group (0..7)
    const int lane = tid & 31, warp = tid >> 5;
    const int i    = ctile * 128 + cl;      // channel

    float beta = beta_raw[i];
    beta = fminf(fmaxf(beta, 0.001f), 0.999f);
    float p  = fminf(fabsf(p_raw[i]), 0.999f);
    float bb = fminf(fmaxf(fabsf(b_raw[i]), 0.001f), 1.0f);
    const float inv_p = 1.0f / p;

    __shared__ int       s1_sm[CC];
    __shared__ unsigned  masks[TT][16];
    __shared__ int       off_sm[TT + 1];
    __shared__ short     lst[CC];
    __shared__ float     cur_sm[128][33];
    __shared__ int       cand_sm[8][128];
    __shared__ float     memlast_sm[128];

    const float* xrow = x   + (size_t)(b * CC + i) * TLEN;
    float*       orow = out + (size_t)(b * CC + i) * TLEN;
    const float* WTi  = g_WT + i;

    switch (tg) {
    case 0: run_loop<0>(cl, lane, warp, b, i, xrow, orow, WTi, beta, p, bb, inv_p,
                        s1_sm, masks, off_sm, lst, cur_sm, cand_sm, memlast_sm); break;
    case 1: run_loop<1>(cl, lane, warp, b, i, xrow, orow, WTi, beta, p, bb, inv_p,
                        s1_sm, masks, off_sm, lst, cur_sm, cand_sm, memlast_sm); break;
    case 2: run_loop<2>(cl, lane, warp, b, i, xrow, orow, WTi, beta, p, bb, inv_p,
                        s1_sm, masks, off_sm, lst, cur_sm, cand_sm, memlast_sm); break;
    case 3: run_loop<3>(cl, lane, warp, b, i, xrow, orow, WTi, beta, p, bb, inv_p,
                        s1_sm, masks, off_sm, lst, cur_sm, cand_sm, memlast_sm); break;
    case 4: run_loop<4>(cl, lane, warp, b, i, xrow, orow, WTi, beta, p, bb, inv_p,
                        s1_sm, masks, off_sm, lst, cur_sm, cand_sm, memlast_sm); break;
    case 5: run_loop<5>(cl, lane, warp, b, i, xrow, orow, WTi, beta, p, bb, inv_p,
                        s1_sm, masks, off_sm, lst, cur_sm, cand_sm, memlast_sm); break;
    case 6: run_loop<6>(cl, lane, warp, b, i, xrow, orow, WTi, beta, p, bb, inv_p,
                        s1_sm, masks, off_sm, lst, cur_sm, cand_sm, memlast_sm); break;
    default: run_loop<7>(cl, lane, warp, b, i, xrow, orow, WTi, beta, p, bb, inv_p,
                        s1_sm, masks, off_sm, lst, cur_sm, cand_sm, memlast_sm); break;
    }
}

// ---------------------------------------------------------------------------
extern "C" void kernel_launch(void* const* d_in, const int* in_sizes, int n_in,
                              void* d_out, int out_size)
{
    const float* x        = (const float*)d_in[0];
    const float* beta_raw = (const float*)d_in[1];
    const float* rec_w    = (const float*)d_in[2];
    const float* p_raw    = (const float*)d_in[3];
    const float* b_raw    = (const float*)d_in[4];
    float* out = (float*)d_out;

    transpose_kernel<<<dim3(16, 16), dim3(32, 8)>>>(rec_w);
    // 148 CTAs (37 clusters of 4): clusters with b>=32 exit immediately
    snn_kernel<<<148, 1024>>>(x, beta_raw, p_raw, b_raw, out);
}

// round 5
// speedup vs baseline: 6.7570x; 1.0386x over previous
#include <cuda_runtime.h>
#include <cstdint>

#define CC    512
#define TLEN  1024
#define TT    32
#define NBLK  32
#define BATCH 32

// Scratch (no cudaMalloc allowed): transposed recurrent weight + spike-time exchange
__device__ float g_WT[CC * CC];
__device__ int   g_s1buf[2][BATCH][CC];

// ---------------------------------------------------------------------------
// Transpose rec_weight (W[i][j]) -> g_WT[j][i] so the gather is coalesced in i
// ---------------------------------------------------------------------------
__global__ void transpose_kernel(const float* __restrict__ W) {
    __shared__ float tile[32][33];
    int j0 = blockIdx.x * 32, i0 = blockIdx.y * 32;
    int tx = threadIdx.x, ty = threadIdx.y;
#pragma unroll
    for (int k = 0; k < 32; k += 8)
        tile[ty + k][tx] = W[(i0 + ty + k) * CC + (j0 + tx)];
    __syncthreads();
#pragma unroll
    for (int k = 0; k < 32; k += 8)
        g_WT[(j0 + ty + k) * CC + (i0 + tx)] = tile[tx][ty + k];
}

// ---------------------------------------------------------------------------
// R5: thread = (channel, t-group of 4). 1024-thread CTA, cluster(4) = 1 batch.
// Changes vs R4 (all value-identical): masked gather (no serial tails),
// powf->smem table for adaptation, s-outer membrane, x prefetch.
// ---------------------------------------------------------------------------
template<int TG>
__device__ __forceinline__ void run_loop(
    int cl, int lane, int warp, int b, int i,
    const float* __restrict__ xrow, float* __restrict__ orow,
    const float* __restrict__ WTi,
    float beta, float p, float bb, float inv_p,
    int*       s1_sm,           // [512]
    unsigned  (*masks)[16],     // [32][16]
    int*       off_sm,          // [33]
    short*     lst,             // [512]
    float     (*cur_sm)[33],    // [128][33]
    int       (*cand_sm)[128],  // [8][128]
    float*     memlast_sm,      // [128]
    float     (*pw_sm)[128])    // [33][128]: p_cl^k
{
    constexpr int BASE = TG * 4;

    // beta-power table, built exactly like R1-R4 (powf with float exponent)
    float bp[BASE + 4];
#pragma unroll
    for (int k = 0; k < BASE + 4; k++) bp[k] = powf(beta, (float)k);
    float ppo[4];
#pragma unroll
    for (int u = 0; u < 4; u++) ppo[u] = powf(p, (float)(BASE + u + 1));

    float mem_last = 0.0f, a_prev = 0.0f;
    int   s1_own = -1;

    float* crow = cur_sm[cl];
    const int tid = TG * 128 + cl;

    // prefetch x block 0
    float4 xv = *(const float4*)(xrow + BASE);

    for (int iter = 0; iter < NBLK; iter++) {
        float cur[4];
        cur[0] = xv.x; cur[1] = xv.y; cur[2] = xv.z; cur[3] = xv.w;

        float a_cur;
        if (iter > 0) {
            // ---- stage previous-block spike times (whole batch) ----
            const int pb = (iter - 1) & 1;
            if (TG < 4) s1_sm[tid] = g_s1buf[pb][b][tid];
            __syncthreads();

            // ---- deterministic bucket masks via ballots: warps 0..15 own rounds ----
            if (warp < 16) {
                int s = s1_sm[warp * 32 + lane];
#pragma unroll
                for (int t = 0; t < TT; t++) {
                    unsigned m = __ballot_sync(0xffffffffu, s == t);
                    if (lane == 0) masks[t][warp] = m;
                }
            }
            __syncthreads();

            // ---- warp 0: counts, scan, compacted list (asc r, asc bit => asc j) ----
            if (TG == 0 && warp == 0) {
                int cnt = 0;
#pragma unroll
                for (int r = 0; r < 16; r++) cnt += __popc(masks[lane][r]);
                int sc = cnt;
#pragma unroll
                for (int d = 1; d < 32; d <<= 1) {
                    int o = __shfl_up_sync(0xffffffffu, sc, d);
                    if (lane >= d) sc += o;
                }
                int excl = sc - cnt;
                off_sm[lane] = excl;
                if (lane == 31) off_sm[32] = sc;
                int pos = excl;
#pragma unroll
                for (int r = 0; r < 16; r++) {
                    unsigned m = masks[lane][r];
                    while (m) {
                        int j = r * 32 + __ffs(m) - 1;
                        m &= m - 1;
                        lst[pos++] = (short)j;
                    }
                }
            }
            __syncthreads();

            // ---- recurrent gather: 4 buckets as 2 pairs, masked rounds of 8.
            //      Adds are in exact ascending-j order; masked lanes add 0.0f
            //      (FP identity here) -> value-identical to R4's chains. ----
#pragma unroll
            for (int u = 0; u < 2; u++) {
                const int tA = BASE + u, tB = BASE + u + 2;
                int kA = off_sm[tA]; const int eA = off_sm[tA + 1];
                int kB = off_sm[tB]; const int eB = off_sm[tB + 1];
                float aA = 0.0f, aB = 0.0f;
#pragma unroll 1
                while (kA < eA || kB < eB) {
                    float wa[8], wb[8];
#pragma unroll
                    for (int v = 0; v < 8; v++) {
                        wa[v] = 0.0f;
                        if (kA + v < eA) wa[v] = WTi[(int)lst[kA + v] * CC];
                    }
#pragma unroll
                    for (int v = 0; v < 8; v++) {
                        wb[v] = 0.0f;
                        if (kB + v < eB) wb[v] = WTi[(int)lst[kB + v] * CC];
                    }
#pragma unroll
                    for (int v = 0; v < 8; v++) aA += wa[v];
#pragma unroll
                    for (int v = 0; v < 8; v++) aB += wb[v];
                    kA += 8; kB += 8;
                }
                cur[u]     += aA;
                cur[u + 2] += aB;
            }

            // ---- zeroing / v_init / adaptation (powf values from table) ----
            if (s1_own >= 0) {
#pragma unroll
                for (int u = 0; u < 4; u++)
                    if (BASE + u < s1_own) cur[u] = 0.0f;
            }
            float v_init = (s1_own >= 0) ? 0.0f : mem_last;
            float pw_up  = pw_sm[s1_own + 1][cl];        // p^(s1+1)
            float pw_dn  = pw_sm[TT - 1 - s1_own][cl];   // p^(31-s1)
            float a_at   = pw_up * a_prev + inv_p;
            float new_a  = a_at * pw_dn;
            a_cur  = (s1_own >= 0) ? new_a : pw_sm[TT][cl] * a_prev;
            a_prev = a_cur;
            if (TG == 0) cur[0] += beta * v_init;
        } else {
            a_cur = 0.0f;      // a_kernel0 = 0 -> v_th = 1 exactly
        }

        // ---- publish cur to smem tile (padded, conflict-free) ----
#pragma unroll
        for (int u = 0; u < 4; u++) crow[BASE + u] = cur[u];
        __syncthreads();

        // ---- membrane: s-outer (one LDS per s), per-t ascending-s fmaf chain ----
        float m[4] = {0.0f, 0.0f, 0.0f, 0.0f};
#pragma unroll
        for (int s = 0; s < BASE + 4; s++) {
            float cs = crow[s];
#pragma unroll
            for (int u = 0; u < 4; u++)
                if (s <= BASE + u) m[u] = fmaf(bp[BASE + u - s], cs, m[u]);
        }
        int cand = 64;
#pragma unroll
        for (int u = 0; u < 4; u++) {
            float vth = 1.0f + bb * (ppo[u] * a_cur);
            if (((m[u] - vth) > 0.0f) && cand == 64) cand = BASE + u;
        }
        cand_sm[TG][cl] = cand;
        if (TG == 7) memlast_sm[cl] = m[3];
        __syncthreads();

        // ---- combine: first crossing over all 8 t-groups; mem[31] broadcast ----
        int s1n = min(min(min(cand_sm[0][cl], cand_sm[1][cl]),
                          min(cand_sm[2][cl], cand_sm[3][cl])),
                      min(min(cand_sm[4][cl], cand_sm[5][cl]),
                          min(cand_sm[6][cl], cand_sm[7][cl])));
        int s1_new = (s1n == 64) ? -1 : s1n;
        mem_last = memlast_sm[cl];
        s1_own   = s1_new;

        // ---- write own 4 spikes ----
        {
            float4 v;
            v.x = (BASE + 0 == s1_new) ? 1.0f : 0.0f;
            v.y = (BASE + 1 == s1_new) ? 1.0f : 0.0f;
            v.z = (BASE + 2 == s1_new) ? 1.0f : 0.0f;
            v.w = (BASE + 3 == s1_new) ? 1.0f : 0.0f;
            *(float4*)(orow + iter * TT + BASE) = v;
        }
        if (TG == 0) g_s1buf[iter & 1][b][i] = s1_new;

        // ---- prefetch next x, publish + batch-scope sync ----
        if (iter < NBLK - 1) {
            xv = *(const float4*)(xrow + (iter + 1) * TT + BASE);
            asm volatile("fence.acq_rel.cluster;" ::: "memory");
            asm volatile("barrier.cluster.arrive.aligned;" ::: "memory");
            asm volatile("barrier.cluster.wait.aligned;" ::: "memory");
        }
    }
}

__global__ void __cluster_dims__(4, 1, 1) __launch_bounds__(1024, 1)
snn_kernel(const float* __restrict__ x,
           const float* __restrict__ beta_raw,
           const float* __restrict__ p_raw,
           const float* __restrict__ b_raw,
           float* __restrict__ out)
{
    const int tid  = threadIdx.x;
    const int b    = blockIdx.x >> 2;
    if (b >= BATCH) return;                 // padding clusters exit whole
    const int ctile = blockIdx.x & 3;
    const int cl   = tid & 127;             // channel-local
    const int tg   = tid >> 7;              // t-group (0..7)
    const int lane = tid & 31, warp = tid >> 5;
    const int i    = ctile * 128 + cl;      // channel

    float beta = beta_raw[i];
    beta = fminf(fmaxf(beta, 0.001f), 0.999f);
    float p  = fminf(fabsf(p_raw[i]), 0.999f);
    float bb = fminf(fmaxf(fabsf(b_raw[i]), 0.001f), 1.0f);
    const float inv_p = 1.0f / p;

    __shared__ int       s1_sm[CC];
    __shared__ unsigned  masks[TT][16];
    __shared__ int       off_sm[TT + 1];
    __shared__ short     lst[CC];
    __shared__ float     cur_sm[128][33];
    __shared__ int       cand_sm[8][128];
    __shared__ float     memlast_sm[128];
    __shared__ float     pw_sm[TT + 1][128];   // p_cl^k, k=0..32

    // fill per-channel p-power table once (bitwise same powf as before)
#pragma unroll 1
    for (int k = tid; k < (TT + 1) * 128; k += 1024) {
        int ke = k >> 7, c0 = k & 127;
        float pc = fminf(fabsf(p_raw[ctile * 128 + c0]), 0.999f);
        pw_sm[ke][c0] = powf(pc, (float)ke);
    }
    __syncthreads();

    const float* xrow = x   + (size_t)(b * CC + i) * TLEN;
    float*       orow = out + (size_t)(b * CC + i) * TLEN;
    const float* WTi  = g_WT + i;

    switch (tg) {
    case 0: run_loop<0>(cl, lane, warp, b, i, xrow, orow, WTi, beta, p, bb, inv_p,
                        s1_sm, masks, off_sm, lst, cur_sm, cand_sm, memlast_sm, pw_sm); break;
    case 1: run_loop<1>(cl, lane, warp, b, i, xrow, orow, WTi, beta, p, bb, inv_p,
                        s1_sm, masks, off_sm, lst, cur_sm, cand_sm, memlast_sm, pw_sm); break;
    case 2: run_loop<2>(cl, lane, warp, b, i, xrow, orow, WTi, beta, p, bb, inv_p,
                        s1_sm, masks, off_sm, lst, cur_sm, cand_sm, memlast_sm, pw_sm); break;
    case 3: run_loop<3>(cl, lane, warp, b, i, xrow, orow, WTi, beta, p, bb, inv_p,
                        s1_sm, masks, off_sm, lst, cur_sm, cand_sm, memlast_sm, pw_sm); break;
    case 4: run_loop<4>(cl, lane, warp, b, i, xrow, orow, WTi, beta, p, bb, inv_p,
                        s1_sm, masks, off_sm, lst, cur_sm, cand_sm, memlast_sm, pw_sm); break;
    case 5: run_loop<5>(cl, lane, warp, b, i, xrow, orow, WTi, beta, p, bb, inv_p,
                        s1_sm, masks, off_sm, lst, cur_sm, cand_sm, memlast_sm, pw_sm); break;
    case 6: run_loop<6>(cl, lane, warp, b, i, xrow, orow, WTi, beta, p, bb, inv_p,
                        s1_sm, masks, off_sm, lst, cur_sm, cand_sm, memlast_sm, pw_sm); break;
    default: run_loop<7>(cl, lane, warp, b, i, xrow, orow, WTi, beta, p, bb, inv_p,
                        s1_sm, masks, off_sm, lst, cur_sm, cand_sm, memlast_sm, pw_sm); break;
    }
}

// ---------------------------------------------------------------------------
extern "C" void kernel_launch(void* const* d_in, const int* in_sizes, int n_in,
                              void* d_out, int out_size)
{
    const float* x        = (const float*)d_in[0];
    const float* beta_raw = (const float*)d_in[1];
    const float* rec_w    = (const float*)d_in[2];
    const float* p_raw    = (const float*)d_in[3];
    const float* b_raw    = (const float*)d_in[4];
    float* out = (float*)d_out;

    transpose_kernel<<<dim3(16, 16), dim3(32, 8)>>>(rec_w);
    // 148 CTAs (37 clusters of 4): clusters with b>=32 exit immediately
    snn_kernel<<<148, 1024>>>(x, beta_raw, p_raw, b_raw, out);
}

// round 6
// speedup vs baseline: 7.8910x; 1.1678x over previous
#include <cuda_runtime.h>
#include <cstdint>

#define CC    512
#define TLEN  1024
#define TT    32
#define NBLK  32
#define BATCH 32

// Scratch (no cudaMalloc allowed). Row CC (index 512) of g_WT is NEVER written:
// device globals are zero-initialized, so it is a permanent zero row used as
// the gather-padding target.
__device__ float g_WT[(CC + 1) * CC];
__device__ int   g_s1buf[2][BATCH][CC];

// ---------------------------------------------------------------------------
// Transpose rec_weight (W[i][j]) -> g_WT[j][i] so the gather is coalesced in i
// ---------------------------------------------------------------------------
__global__ void transpose_kernel(const float* __restrict__ W) {
    __shared__ float tile[32][33];
    int j0 = blockIdx.x * 32, i0 = blockIdx.y * 32;
    int tx = threadIdx.x, ty = threadIdx.y;
#pragma unroll
    for (int k = 0; k < 32; k += 8)
        tile[ty + k][tx] = W[(i0 + ty + k) * CC + (j0 + tx)];
    __syncthreads();
#pragma unroll
    for (int k = 0; k < 32; k += 8)
        g_WT[(j0 + ty + k) * CC + (i0 + tx)] = tile[tx][ty + k];
}

// ---------------------------------------------------------------------------
// R6: thread = (channel, t-group of 4). 1024-thread CTA, cluster(4) = 1 batch.
// vs R5 (all value-identical): buckets padded to 8 with zero-row index (no
// per-element predication), vector LDS of indices, atomicOr masks (no ballots),
// LDS.128 membrane reads, STS.128 cur publish.
// ---------------------------------------------------------------------------
template<int TG>
__device__ __forceinline__ void run_loop(
    int cl, int lane, int warp, int b, int i,
    const float* __restrict__ xrow, float* __restrict__ orow,
    const float* __restrict__ WTi,
    float beta, float p, float bb, float inv_p,
    unsigned  (*masks)[16],     // [32][16]
    int*       off_sm,          // [33] padded exclusive offsets
    short*     lst,             // [768] compacted+padded j list
    float     (*cur_sm)[36],    // [128][36] (16B-aligned rows, conflict-free)
    int       (*cand_sm)[128],  // [8][128]
    float*     memlast_sm,      // [128]
    float     (*pw_sm)[128])    // [33][128]: p_cl^k
{
    constexpr int BASE = TG * 4;

    // beta-power table, built exactly like R1-R5 (powf with float exponent)
    float bp[BASE + 4];
#pragma unroll
    for (int k = 0; k < BASE + 4; k++) bp[k] = powf(beta, (float)k);
    float ppo[4];
#pragma unroll
    for (int u = 0; u < 4; u++) ppo[u] = powf(p, (float)(BASE + u + 1));

    float mem_last = 0.0f, a_prev = 0.0f;
    int   s1_own = -1;

    float* crow = cur_sm[cl];
    const int tid = TG * 128 + cl;

    // prefetch x block 0
    float4 xv = *(const float4*)(xrow + BASE);

    for (int iter = 0; iter < NBLK; iter++) {
        float cur[4];
        cur[0] = xv.x; cur[1] = xv.y; cur[2] = xv.z; cur[3] = xv.w;

        float a_cur;
        if (iter > 0) {
            // ---- phase A: TG<4 read prev spike times; TG>=4 zero masks ----
            const int pb = (iter - 1) & 1;
            int sown = -2;
            if (TG < 4) sown = g_s1buf[pb][b][tid];
            else        ((unsigned*)masks)[tid - 512] = 0;
            __syncthreads();

            // ---- phase B: set mask bit (OR commutes -> deterministic) ----
            if (TG < 4 && sown >= 0)
                atomicOr(&masks[sown][tid >> 5], 1u << (tid & 31));
            __syncthreads();

            // ---- warp 0: padded counts, scan, compacted list (asc r, asc bit) ----
            if (TG == 0 && warp == 0) {
                int cnt = 0;
#pragma unroll
                for (int r = 0; r < 16; r++) cnt += __popc(masks[lane][r]);
                int pcnt = (cnt + 7) & ~7;             // pad to multiple of 8
                int sc = pcnt;
#pragma unroll
                for (int d = 1; d < 32; d <<= 1) {
                    int o = __shfl_up_sync(0xffffffffu, sc, d);
                    if (lane >= d) sc += o;
                }
                int excl = sc - pcnt;
                off_sm[lane] = excl;
                if (lane == 31) off_sm[32] = sc;
                int pos = excl;
#pragma unroll
                for (int r = 0; r < 16; r++) {
                    unsigned m = masks[lane][r];
                    while (m) {
                        int j = r * 32 + __ffs(m) - 1;
                        m &= m - 1;
                        lst[pos++] = (short)j;
                    }
                }
                for (int e = excl + pcnt; pos < e; pos++)
                    lst[pos] = (short)CC;              // zero-row padding
            }
            __syncthreads();

            // ---- recurrent gather: 4 buckets as 2 pairs; rounds of 8,
            //      unconditional loads (pads hit the zero row), uniform branches.
            //      Adds in exact ascending-j order + zeros -> value-identical. ----
#pragma unroll
            for (int u = 0; u < 2; u++) {
                const int tA = BASE + u, tB = BASE + u + 2;
                int kA = off_sm[tA]; const int eA = off_sm[tA + 1];
                int kB = off_sm[tB]; const int eB = off_sm[tB + 1];
                float aA = 0.0f, aB = 0.0f;
#pragma unroll 1
                while (kA < eA || kB < eB) {
                    const bool hA = kA < eA, hB = kB < eB;   // warp-uniform
                    float wa[8], wb[8];
                    if (hA) {
                        uint4 q = *(const uint4*)(lst + kA);
                        wa[0] = WTi[(q.x & 0xffffu) * CC];
                        wa[1] = WTi[(q.x >> 16)     * CC];
                        wa[2] = WTi[(q.y & 0xffffu) * CC];
                        wa[3] = WTi[(q.y >> 16)     * CC];
                        wa[4] = WTi[(q.z & 0xffffu) * CC];
                        wa[5] = WTi[(q.z >> 16)     * CC];
                        wa[6] = WTi[(q.w & 0xffffu) * CC];
                        wa[7] = WTi[(q.w >> 16)     * CC];
                    }
                    if (hB) {
                        uint4 q = *(const uint4*)(lst + kB);
                        wb[0] = WTi[(q.x & 0xffffu) * CC];
                        wb[1] = WTi[(q.x >> 16)     * CC];
                        wb[2] = WTi[(q.y & 0xffffu) * CC];
                        wb[3] = WTi[(q.y >> 16)     * CC];
                        wb[4] = WTi[(q.z & 0xffffu) * CC];
                        wb[5] = WTi[(q.z >> 16)     * CC];
                        wb[6] = WTi[(q.w & 0xffffu) * CC];
                        wb[7] = WTi[(q.w >> 16)     * CC];
                    }
                    if (hA) {
#pragma unroll
                        for (int v = 0; v < 8; v++) aA += wa[v];
                        kA += 8;
                    }
                    if (hB) {
#pragma unroll
                        for (int v = 0; v < 8; v++) aB += wb[v];
                        kB += 8;
                    }
                }
                cur[u]     += aA;
                cur[u + 2] += aB;
            }

            // ---- zeroing / v_init / adaptation (powf values from table) ----
            if (s1_own >= 0) {
#pragma unroll
                for (int u = 0; u < 4; u++)
                    if (BASE + u < s1_own) cur[u] = 0.0f;
            }
            float v_init = (s1_own >= 0) ? 0.0f : mem_last;
            float pw_up  = pw_sm[s1_own + 1][cl];        // p^(s1+1)
            float pw_dn  = pw_sm[TT - 1 - s1_own][cl];   // p^(31-s1)
            float a_at   = pw_up * a_prev + inv_p;
            float new_a  = a_at * pw_dn;
            a_cur  = (s1_own >= 0) ? new_a : pw_sm[TT][cl] * a_prev;
            a_prev = a_cur;
            if (TG == 0) cur[0] += beta * v_init;
        } else {
            a_cur = 0.0f;      // a_kernel0 = 0 -> v_th = 1 exactly
        }

        // ---- publish cur (one STS.128; 16B-aligned, conflict-free) ----
        *(float4*)(crow + BASE) = make_float4(cur[0], cur[1], cur[2], cur[3]);
        __syncthreads();

        // ---- membrane: LDS.128 chunks, per-t ascending-s fmaf chain (exact) ----
        float m[4] = {0.0f, 0.0f, 0.0f, 0.0f};
#pragma unroll
        for (int q = 0; q <= TG; q++) {
            float4 c4 = *(const float4*)(crow + q * 4);
            const float cc4[4] = { c4.x, c4.y, c4.z, c4.w };
#pragma unroll
            for (int w = 0; w < 4; w++) {
                const int s = q * 4 + w;
#pragma unroll
                for (int u = 0; u < 4; u++)
                    if (q < TG || w <= u)
                        m[u] = fmaf(bp[BASE + u - s], cc4[w], m[u]);
            }
        }
        int cand = 64;
#pragma unroll
        for (int u = 0; u < 4; u++) {
            float vth = 1.0f + bb * (ppo[u] * a_cur);
            if (((m[u] - vth) > 0.0f) && cand == 64) cand = BASE + u;
        }
        cand_sm[TG][cl] = cand;
        if (TG == 7) memlast_sm[cl] = m[3];
        __syncthreads();

        // ---- combine: first crossing over all 8 t-groups; mem[31] broadcast ----
        int s1n = min(min(min(cand_sm[0][cl], cand_sm[1][cl]),
                          min(cand_sm[2][cl], cand_sm[3][cl])),
                      min(min(cand_sm[4][cl], cand_sm[5][cl]),
                          min(cand_sm[6][cl], cand_sm[7][cl])));
        int s1_new = (s1n == 64) ? -1 : s1n;
        mem_last = memlast_sm[cl];
        s1_own   = s1_new;

        // ---- write own 4 spikes ----
        {
            float4 v;
            v.x = (BASE + 0 == s1_new) ? 1.0f : 0.0f;
            v.y = (BASE + 1 == s1_new) ? 1.0f : 0.0f;
            v.z = (BASE + 2 == s1_new) ? 1.0f : 0.0f;
            v.w = (BASE + 3 == s1_new) ? 1.0f : 0.0f;
            *(float4*)(orow + iter * TT + BASE) = v;
        }
        if (TG == 0) g_s1buf[iter & 1][b][i] = s1_new;

        // ---- prefetch next x, publish + batch-scope sync ----
        if (iter < NBLK - 1) {
            xv = *(const float4*)(xrow + (iter + 1) * TT + BASE);
            asm volatile("fence.acq_rel.cluster;" ::: "memory");
            asm volatile("barrier.cluster.arrive.aligned;" ::: "memory");
            asm volatile("barrier.cluster.wait.aligned;" ::: "memory");
        }
    }
}

__global__ void __cluster_dims__(4, 1, 1) __launch_bounds__(1024, 1)
snn_kernel(const float* __restrict__ x,
           const float* __restrict__ beta_raw,
           const float* __restrict__ p_raw,
           const float* __restrict__ b_raw,
           float* __restrict__ out)
{
    const int tid  = threadIdx.x;
    const int b    = blockIdx.x >> 2;
    if (b >= BATCH) return;                 // padding clusters exit whole
    const int ctile = blockIdx.x & 3;
    const int cl   = tid & 127;             // channel-local
    const int tg   = tid >> 7;              // t-group (0..7)
    const int lane = tid & 31, warp = tid >> 5;
    const int i    = ctile * 128 + cl;      // channel

    float beta = beta_raw[i];
    beta = fminf(fmaxf(beta, 0.001f), 0.999f);
    float p  = fminf(fabsf(p_raw[i]), 0.999f);
    float bb = fminf(fmaxf(fabsf(b_raw[i]), 0.001f), 1.0f);
    const float inv_p = 1.0f / p;

    __shared__ unsigned            masks[TT][16];
    __shared__ int                 off_sm[TT + 1];
    __shared__ __align__(16) short lst[768];
    __shared__ __align__(16) float cur_sm[128][36];
    __shared__ int                 cand_sm[8][128];
    __shared__ float               memlast_sm[128];
    __shared__ float               pw_sm[TT + 1][128];   // p_cl^k, k=0..32

    // fill per-channel p-power table once (bitwise same powf as before)
#pragma unroll 1
    for (int k = tid; k < (TT + 1) * 128; k += 1024) {
        int ke = k >> 7, c0 = k & 127;
        float pc = fminf(fabsf(p_raw[ctile * 128 + c0]), 0.999f);
        pw_sm[ke][c0] = powf(pc, (float)ke);
    }
    __syncthreads();

    const float* xrow = x   + (size_t)(b * CC + i) * TLEN;
    float*       orow = out + (size_t)(b * CC + i) * TLEN;
    const float* WTi  = g_WT + i;

    switch (tg) {
    case 0: run_loop<0>(cl, lane, warp, b, i, xrow, orow, WTi, beta, p, bb, inv_p,
                        masks, off_sm, lst, cur_sm, cand_sm, memlast_sm, pw_sm); break;
    case 1: run_loop<1>(cl, lane, warp, b, i, xrow, orow, WTi, beta, p, bb, inv_p,
                        masks, off_sm, lst, cur_sm, cand_sm, memlast_sm, pw_sm); break;
    case 2: run_loop<2>(cl, lane, warp, b, i, xrow, orow, WTi, beta, p, bb, inv_p,
                        masks, off_sm, lst, cur_sm, cand_sm, memlast_sm, pw_sm); break;
    case 3: run_loop<3>(cl, lane, warp, b, i, xrow, orow, WTi, beta, p, bb, inv_p,
                        masks, off_sm, lst, cur_sm, cand_sm, memlast_sm, pw_sm); break;
    case 4: run_loop<4>(cl, lane, warp, b, i, xrow, orow, WTi, beta, p, bb, inv_p,
                        masks, off_sm, lst, cur_sm, cand_sm, memlast_sm, pw_sm); break;
    case 5: run_loop<5>(cl, lane, warp, b, i, xrow, orow, WTi, beta, p, bb, inv_p,
                        masks, off_sm, lst, cur_sm, cand_sm, memlast_sm, pw_sm); break;
    case 6: run_loop<6>(cl, lane, warp, b, i, xrow, orow, WTi, beta, p, bb, inv_p,
                        masks, off_sm, lst, cur_sm, cand_sm, memlast_sm, pw_sm); break;
    default: run_loop<7>(cl, lane, warp, b, i, xrow, orow, WTi, beta, p, bb, inv_p,
                        masks, off_sm, lst, cur_sm, cand_sm, memlast_sm, pw_sm); break;
    }
}

// ---------------------------------------------------------------------------
extern "C" void kernel_launch(void* const* d_in, const int* in_sizes, int n_in,
                              void* d_out, int out_size)
{
    const float* x        = (const float*)d_in[0];
    const float* beta_raw = (const float*)d_in[1];
    const float* rec_w    = (const float*)d_in[2];
    const float* p_raw    = (const float*)d_in[3];
    const float* b_raw    = (const float*)d_in[4];
    float* out = (float*)d_out;

    transpose_kernel<<<dim3(16, 16), dim3(32, 8)>>>(rec_w);
    // 148 CTAs (37 clusters of 4): clusters with b>=32 exit immediately
    snn_kernel<<<148, 1024>>>(x, beta_raw, p_raw, b_raw, out);
}

// round 7
// speedup vs baseline: 8.8210x; 1.1179x over previous
#include <cuda_runtime.h>
#include <cstdint>

#define CC    512
#define TLEN  1024
#define TT    32
#define NBLK  32
#define BATCH 32

// Packed dual-FP32 add (Blackwell f32x2): two independent IEEE adds.
#define ADD_F32X2(out, a, b) \
    asm("add.rn.f32x2 %0, %1, %2;" : "=l"(out) : "l"(a), "l"(b))

// Scratch (no cudaMalloc allowed). Row CC (index 512) of g_WT is NEVER written:
// device globals are zero-initialized, so it is a permanent zero row used as
// the gather-padding target.
__device__ float g_WT[(CC + 1) * CC];
__device__ int   g_s1buf[2][BATCH][CC];

// ---------------------------------------------------------------------------
// Transpose rec_weight (W[i][j]) -> g_WT[j][i] so the gather is coalesced in i
// ---------------------------------------------------------------------------
__global__ void transpose_kernel(const float* __restrict__ W) {
    __shared__ float tile[32][33];
    int j0 = blockIdx.x * 32, i0 = blockIdx.y * 32;
    int tx = threadIdx.x, ty = threadIdx.y;
#pragma unroll
    for (int k = 0; k < 32; k += 8)
        tile[ty + k][tx] = W[(i0 + ty + k) * CC + (j0 + tx)];
    __syncthreads();
#pragma unroll
    for (int k = 0; k < 32; k += 8)
        g_WT[(j0 + ty + k) * CC + (i0 + tx)] = tile[tx][ty + k];
}

// ---------------------------------------------------------------------------
// R7: gather phase re-mapped: warp = one t-bucket (uniform length), lane = 4
// channels via LDG.128 + add.rn.f32x2 (per-channel chains order-identical).
// Membrane phase keeps R6 layout: thread = (channel, t-group of 4).
// 1024-thread CTA, cluster(4) = 1 batch. Bitwise-identical spike decisions.
// ---------------------------------------------------------------------------
template<int TG>
__device__ __forceinline__ void run_loop(
    int cl, int lane, int warp, int b, int i, int ctile,
    const float* __restrict__ xrow, float* __restrict__ orow,
    float beta, float p, float bb, float inv_p,
    unsigned  (*masks)[16],     // [32][16]
    int*       off_sm,          // [33] padded exclusive offsets
    short*     lst,             // [768] compacted+padded j list
    float     (*rec_sm)[128],   // [32][128] gather results (t-major)
    float     (*cur_sm)[36],    // [128][36] (16B-aligned rows, conflict-free)
    int       (*cand_sm)[128],  // [8][128]
    float*     memlast_sm,      // [128]
    float     (*pw_sm)[128])    // [33][128]: p_cl^k
{
    constexpr int BASE = TG * 4;

    // beta-power table, built exactly like R1-R6 (powf with float exponent)
    float bp[BASE + 4];
#pragma unroll
    for (int k = 0; k < BASE + 4; k++) bp[k] = powf(beta, (float)k);
    float ppo[4];
#pragma unroll
    for (int u = 0; u < 4; u++) ppo[u] = powf(p, (float)(BASE + u + 1));

    float mem_last = 0.0f, a_prev = 0.0f;
    int   s1_own = -1;

    float* crow = cur_sm[cl];
    const int tid = TG * 128 + cl;
    // gather-phase base: lane owns 4 consecutive channels of this CTA's slice
    const float* Wb = g_WT + ctile * 128 + lane * 4;

    // prefetch x block 0
    float4 xv = *(const float4*)(xrow + BASE);

    for (int iter = 0; iter < NBLK; iter++) {
        float cur[4];
        cur[0] = xv.x; cur[1] = xv.y; cur[2] = xv.z; cur[3] = xv.w;

        float a_cur;
        if (iter > 0) {
            // ---- phase A: TG<4 read prev spike times; TG>=4 zero masks ----
            const int pb = (iter - 1) & 1;
            int sown = -2;
            if (TG < 4) sown = g_s1buf[pb][b][tid];
            else        ((unsigned*)masks)[tid - 512] = 0;
            __syncthreads();

            // ---- phase B: set mask bit (OR commutes -> deterministic) ----
            if (TG < 4 && sown >= 0)
                atomicOr(&masks[sown][tid >> 5], 1u << (tid & 31));
            __syncthreads();

            // ---- warp 0: padded counts, scan, compacted list (asc r, asc bit) ----
            if (TG == 0 && warp == 0) {
                int cnt = 0;
#pragma unroll
                for (int r = 0; r < 16; r++) cnt += __popc(masks[lane][r]);
                int pcnt = (cnt + 7) & ~7;             // pad to multiple of 8
                int sc = pcnt;
#pragma unroll
                for (int d = 1; d < 32; d <<= 1) {
                    int o = __shfl_up_sync(0xffffffffu, sc, d);
                    if (lane >= d) sc += o;
                }
                int excl = sc - pcnt;
                off_sm[lane] = excl;
                if (lane == 31) off_sm[32] = sc;
                int pos = excl;
#pragma unroll
                for (int r = 0; r < 16; r++) {
                    unsigned m = masks[lane][r];
                    while (m) {
                        int j = r * 32 + __ffs(m) - 1;
                        m &= m - 1;
                        lst[pos++] = (short)j;
                    }
                }
                for (int e = excl + pcnt; pos < e; pos++)
                    lst[pos] = (short)CC;              // zero-row padding
            }
            __syncthreads();

            // ---- gather: warp = bucket t (uniform), lane = 4 channels.
            //      LDG.128 per spike; per-channel chains ascending-j, f32x2
            //      packed adds (two independent IEEE adds) -> value-identical.
            {
                const int t = warp;
                int k = off_sm[t]; const int e = off_sm[t + 1];
                unsigned long long a01 = 0ull, a23 = 0ull;
#pragma unroll 1
                while (k < e) {                        // warp-uniform, len % 8 == 0
                    uint4 q = *(const uint4*)(lst + k);
                    const int j0 = q.x & 0xffffu, j1 = q.x >> 16;
                    const int j2 = q.y & 0xffffu, j3 = q.y >> 16;
                    const int j4 = q.z & 0xffffu, j5 = q.z >> 16;
                    const int j6 = q.w & 0xffffu, j7 = q.w >> 16;
                    ulonglong2 w0 = *(const ulonglong2*)(Wb + j0 * CC);
                    ulonglong2 w1 = *(const ulonglong2*)(Wb + j1 * CC);
                    ulonglong2 w2 = *(const ulonglong2*)(Wb + j2 * CC);
                    ulonglong2 w3 = *(const ulonglong2*)(Wb + j3 * CC);
                    ulonglong2 w4 = *(const ulonglong2*)(Wb + j4 * CC);
                    ulonglong2 w5 = *(const ulonglong2*)(Wb + j5 * CC);
                    ulonglong2 w6 = *(const ulonglong2*)(Wb + j6 * CC);
                    ulonglong2 w7 = *(const ulonglong2*)(Wb + j7 * CC);
                    ADD_F32X2(a01, a01, w0.x); ADD_F32X2(a23, a23, w0.y);
                    ADD_F32X2(a01, a01, w1.x); ADD_F32X2(a23, a23, w1.y);
                    ADD_F32X2(a01, a01, w2.x); ADD_F32X2(a23, a23, w2.y);
                    ADD_F32X2(a01, a01, w3.x); ADD_F32X2(a23, a23, w3.y);
                    ADD_F32X2(a01, a01, w4.x); ADD_F32X2(a23, a23, w4.y);
                    ADD_F32X2(a01, a01, w5.x); ADD_F32X2(a23, a23, w5.y);
                    ADD_F32X2(a01, a01, w6.x); ADD_F32X2(a23, a23, w6.y);
                    ADD_F32X2(a01, a01, w7.x); ADD_F32X2(a23, a23, w7.y);
                    k += 8;
                }
                ulonglong2 st; st.x = a01; st.y = a23;
                *(ulonglong2*)(&rec_sm[t][lane * 4]) = st;
            }
            __syncthreads();

            // ---- assemble cur = x + rec (single add, as R6's cur+=aA) ----
#pragma unroll
            for (int u = 0; u < 4; u++) cur[u] += rec_sm[BASE + u][cl];

            // ---- zeroing / v_init / adaptation (powf values from table) ----
            if (s1_own >= 0) {
#pragma unroll
                for (int u = 0; u < 4; u++)
                    if (BASE + u < s1_own) cur[u] = 0.0f;
            }
            float v_init = (s1_own >= 0) ? 0.0f : mem_last;
            float pw_up  = pw_sm[s1_own + 1][cl];        // p^(s1+1)
            float pw_dn  = pw_sm[TT - 1 - s1_own][cl];   // p^(31-s1)
            float a_at   = pw_up * a_prev + inv_p;
            float new_a  = a_at * pw_dn;
            a_cur  = (s1_own >= 0) ? new_a : pw_sm[TT][cl] * a_prev;
            a_prev = a_cur;
            if (TG == 0) cur[0] += beta * v_init;
        } else {
            a_cur = 0.0f;      // a_kernel0 = 0 -> v_th = 1 exactly
        }

        // ---- publish cur (one STS.128; 16B-aligned, conflict-free) ----
        *(float4*)(crow + BASE) = make_float4(cur[0], cur[1], cur[2], cur[3]);
        __syncthreads();

        // ---- membrane: LDS.128 chunks, per-t ascending-s fmaf chain (exact) ----
        float m[4] = {0.0f, 0.0f, 0.0f, 0.0f};
#pragma unroll
        for (int q = 0; q <= TG; q++) {
            float4 c4 = *(const float4*)(crow + q * 4);
            const float cc4[4] = { c4.x, c4.y, c4.z, c4.w };
#pragma unroll
            for (int w = 0; w < 4; w++) {
                const int s = q * 4 + w;
#pragma unroll
                for (int u = 0; u < 4; u++)
                    if (q < TG || w <= u)
                        m[u] = fmaf(bp[BASE + u - s], cc4[w], m[u]);
            }
        }
        int cand = 64;
#pragma unroll
        for (int u = 0; u < 4; u++) {
            float vth = 1.0f + bb * (ppo[u] * a_cur);
            if (((m[u] - vth) > 0.0f) && cand == 64) cand = BASE + u;
        }
        cand_sm[TG][cl] = cand;
        if (TG == 7) memlast_sm[cl] = m[3];
        __syncthreads();

        // ---- combine: first crossing over all 8 t-groups; mem[31] broadcast ----
        int s1n = min(min(min(cand_sm[0][cl], cand_sm[1][cl]),
                          min(cand_sm[2][cl], cand_sm[3][cl])),
                      min(min(cand_sm[4][cl], cand_sm[5][cl]),
                          min(cand_sm[6][cl], cand_sm[7][cl])));
        int s1_new = (s1n == 64) ? -1 : s1n;
        mem_last = memlast_sm[cl];
        s1_own   = s1_new;

        // ---- write own 4 spikes ----
        {
            float4 v;
            v.x = (BASE + 0 == s1_new) ? 1.0f : 0.0f;
            v.y = (BASE + 1 == s1_new) ? 1.0f : 0.0f;
            v.z = (BASE + 2 == s1_new) ? 1.0f : 0.0f;
            v.w = (BASE + 3 == s1_new) ? 1.0f : 0.0f;
            *(float4*)(orow + iter * TT + BASE) = v;
        }
        if (TG == 0) g_s1buf[iter & 1][b][i] = s1_new;

        // ---- prefetch next x, publish + batch-scope sync ----
        if (iter < NBLK - 1) {
            xv = *(const float4*)(xrow + (iter + 1) * TT + BASE);
            asm volatile("fence.acq_rel.cluster;" ::: "memory");
            asm volatile("barrier.cluster.arrive.aligned;" ::: "memory");
            asm volatile("barrier.cluster.wait.aligned;" ::: "memory");
        }
    }
}

__global__ void __cluster_dims__(4, 1, 1) __launch_bounds__(1024, 1)
snn_kernel(const float* __restrict__ x,
           const float* __restrict__ beta_raw,
           const float* __restrict__ p_raw,
           const float* __restrict__ b_raw,
           float* __restrict__ out)
{
    const int tid  = threadIdx.x;
    const int b    = blockIdx.x >> 2;
    if (b >= BATCH) return;                 // padding clusters exit whole
    const int ctile = blockIdx.x & 3;
    const int cl   = tid & 127;             // channel-local
    const int tg   = tid >> 7;              // t-group (0..7)
    const int lane = tid & 31, warp = tid >> 5;
    const int i    = ctile * 128 + cl;      // channel

    float beta = beta_raw[i];
    beta = fminf(fmaxf(beta, 0.001f), 0.999f);
    float p  = fminf(fabsf(p_raw[i]), 0.999f);
    float bb = fminf(fmaxf(fabsf(b_raw[i]), 0.001f), 1.0f);
    const float inv_p = 1.0f / p;

    __shared__ unsigned            masks[TT][16];
    __shared__ int                 off_sm[TT + 1];
    __shared__ __align__(16) short lst[768];
    __shared__ __align__(16) float rec_sm[TT][128];
    __shared__ __align__(16) float cur_sm[128][36];
    __shared__ int                 cand_sm[8][128];
    __shared__ float               memlast_sm[128];
    __shared__ float               pw_sm[TT + 1][128];   // p_cl^k, k=0..32

    // fill per-channel p-power table once (bitwise same powf as before)
#pragma unroll 1
    for (int k = tid; k < (TT + 1) * 128; k += 1024) {
        int ke = k >> 7, c0 = k & 127;
        float pc = fminf(fabsf(p_raw[ctile * 128 + c0]), 0.999f);
        pw_sm[ke][c0] = powf(pc, (float)ke);
    }
    __syncthreads();

    const float* xrow = x   + (size_t)(b * CC + i) * TLEN;
    float*       orow = out + (size_t)(b * CC + i) * TLEN;

    switch (tg) {
    case 0: run_loop<0>(cl, lane, warp, b, i, ctile, xrow, orow, beta, p, bb, inv_p,
                        masks, off_sm, lst, rec_sm, cur_sm, cand_sm, memlast_sm, pw_sm); break;
    case 1: run_loop<1>(cl, lane, warp, b, i, ctile, xrow, orow, beta, p, bb, inv_p,
                        masks, off_sm, lst, rec_sm, cur_sm, cand_sm, memlast_sm, pw_sm); break;
    case 2: run_loop<2>(cl, lane, warp, b, i, ctile, xrow, orow, beta, p, bb, inv_p,
                        masks, off_sm, lst, rec_sm, cur_sm, cand_sm, memlast_sm, pw_sm); break;
    case 3: run_loop<3>(cl, lane, warp, b, i, ctile, xrow, orow, beta, p, bb, inv_p,
                        masks, off_sm, lst, rec_sm, cur_sm, cand_sm, memlast_sm, pw_sm); break;
    case 4: run_loop<4>(cl, lane, warp, b, i, ctile, xrow, orow, beta, p, bb, inv_p,
                        masks, off_sm, lst, rec_sm, cur_sm, cand_sm, memlast_sm, pw_sm); break;
    case 5: run_loop<5>(cl, lane, warp, b, i, ctile, xrow, orow, beta, p, bb, inv_p,
                        masks, off_sm, lst, rec_sm, cur_sm, cand_sm, memlast_sm, pw_sm); break;
    case 6: run_loop<6>(cl, lane, warp, b, i, ctile, xrow, orow, beta, p, bb, inv_p,
                        masks, off_sm, lst, rec_sm, cur_sm, cand_sm, memlast_sm, pw_sm); break;
    default: run_loop<7>(cl, lane, warp, b, i, ctile, xrow, orow, beta, p, bb, inv_p,
                        masks, off_sm, lst, rec_sm, cur_sm, cand_sm, memlast_sm, pw_sm); break;
    }
}

// ---------------------------------------------------------------------------
extern "C" void kernel_launch(void* const* d_in, const int* in_sizes, int n_in,
                              void* d_out, int out_size)
{
    const float* x        = (const float*)d_in[0];
    const float* beta_raw = (const float*)d_in[1];
    const float* rec_w    = (const float*)d_in[2];
    const float* p_raw    = (const float*)d_in[3];
    const float* b_raw    = (const float*)d_in[4];
    float* out = (float*)d_out;

    transpose_kernel<<<dim3(16, 16), dim3(32, 8)>>>(rec_w);
    // 148 CTAs (37 clusters of 4): clusters with b>=32 exit immediately
    snn_kernel<<<148, 1024>>>(x, beta_raw, p_raw, b_raw, out);
}

// round 8
// speedup vs baseline: 9.6115x; 1.0896x over previous
#include <cuda_runtime.h>
#include <cstdint>

#define CC    512
#define TLEN  1024
#define TT    32
#define NBLK  32
#define BATCH 32
#define JS    288            // j < JS served from smem (9 mask rounds of 32)
#define SW_ROWS (JS + 1)     // +1 zero row for smem-segment padding
#define SW_BYTES (SW_ROWS * 128 * 4)

// Packed dual-FP32 add (Blackwell f32x2): two independent IEEE adds.
#define ADD_F32X2(out, a, b) \
    asm("add.rn.f32x2 %0, %1, %2;" : "=l"(out) : "l"(a), "l"(b))

// Scratch (no cudaMalloc allowed). Row CC (index 512) of g_WT is NEVER written:
// device globals are zero-initialized, so it is a permanent zero row used as
// the gmem gather-padding target.
__device__ float g_WT[(CC + 1) * CC];
__device__ int   g_s1buf[2][BATCH][CC];

// ---------------------------------------------------------------------------
// Transpose rec_weight (W[i][j]) -> g_WT[j][i] so the gather is coalesced in i
// ---------------------------------------------------------------------------
__global__ void transpose_kernel(const float* __restrict__ W) {
    __shared__ float tile[32][33];
    int j0 = blockIdx.x * 32, i0 = blockIdx.y * 32;
    int tx = threadIdx.x, ty = threadIdx.y;
#pragma unroll
    for (int k = 0; k < 32; k += 8)
        tile[ty + k][tx] = W[(i0 + ty + k) * CC + (j0 + tx)];
    __syncthreads();
#pragma unroll
    for (int k = 0; k < 32; k += 8)
        g_WT[(j0 + ty + k) * CC + (i0 + tx)] = tile[tx][ty + k];
}

// ---------------------------------------------------------------------------
// R8: 56% of this CTA's W slice lives in smem (survives the per-iteration L1
// flush from cluster.sync). Buckets split into smem segment (j<288) + gmem
// segment (j>=288), each padded to 8 with a zero row. Gather: warp = bucket,
// lane = 4 channels, LDS.128 then LDG.128, f32x2 adds in ascending-j order.
// Membrane phase unchanged from R7. Bitwise-identical spike decisions.
// ---------------------------------------------------------------------------
template<int TG>
__device__ __forceinline__ void run_loop(
    int cl, int lane, int warp, int b, int i, int ctile,
    const float* __restrict__ xrow, float* __restrict__ orow,
    const float* __restrict__ sW,   // [SW_ROWS][128] smem W slice
    float beta, float p, float bb, float inv_p,
    unsigned  (*masks)[16],     // [32][16]
    int*       offS_sm,         // [32] smem-segment starts
    int*       offG_sm,         // [32] gmem-segment starts
    int*       offE_sm,         // [32] bucket ends
    short*     lst,             // [1024] compacted+padded j list
    float     (*rec_sm)[128],   // [32][128] gather results (t-major)
    float     (*cur_sm)[36],    // [128][36] (16B-aligned rows, conflict-free)
    int       (*cand_sm)[128],  // [8][128]
    float*     memlast_sm,      // [128]
    float     (*pw_sm)[128])    // [33][128]: p_cl^k
{
    constexpr int BASE = TG * 4;

    // beta-power table, built exactly like R1-R7 (powf with float exponent)
    float bp[BASE + 4];
#pragma unroll
    for (int k = 0; k < BASE + 4; k++) bp[k] = powf(beta, (float)k);
    float ppo[4];
#pragma unroll
    for (int u = 0; u < 4; u++) ppo[u] = powf(p, (float)(BASE + u + 1));

    float mem_last = 0.0f, a_prev = 0.0f;
    int   s1_own = -1;

    float* crow = cur_sm[cl];
    const int tid = TG * 128 + cl;
    const float* Wb  = g_WT + ctile * 128 + lane * 4;  // gmem gather base
    const float* sWb = sW + lane * 4;                  // smem gather base

    // prefetch x block 0
    float4 xv = *(const float4*)(xrow + BASE);

    for (int iter = 0; iter < NBLK; iter++) {
        float cur[4];
        cur[0] = xv.x; cur[1] = xv.y; cur[2] = xv.z; cur[3] = xv.w;

        float a_cur;
        if (iter > 0) {
            // ---- phase A: TG<4 read prev spike times; TG>=4 zero masks ----
            const int pb = (iter - 1) & 1;
            int sown = -2;
            if (TG < 4) sown = g_s1buf[pb][b][tid];
            else        ((unsigned*)masks)[tid - 512] = 0;
            __syncthreads();

            // ---- phase B: set mask bit (OR commutes -> deterministic) ----
            if (TG < 4 && sown >= 0)
                atomicOr(&masks[sown][tid >> 5], 1u << (tid & 31));
            __syncthreads();

            // ---- warp 0: split counts, scan, two padded segments per bucket ----
            if (TG == 0 && warp == 0) {
                int cntS = 0, cntG = 0;
#pragma unroll
                for (int r = 0; r < 9; r++)  cntS += __popc(masks[lane][r]);
#pragma unroll
                for (int r = 9; r < 16; r++) cntG += __popc(masks[lane][r]);
                int pS = (cntS + 7) & ~7;
                int pG = (cntG + 7) & ~7;
                int pt = pS + pG;
                int sc = pt;
#pragma unroll
                for (int d = 1; d < 32; d <<= 1) {
                    int o = __shfl_up_sync(0xffffffffu, sc, d);
                    if (lane >= d) sc += o;
                }
                int excl = sc - pt;
                offS_sm[lane] = excl;
                offG_sm[lane] = excl + pS;
                offE_sm[lane] = excl + pt;
                int pos = excl;
#pragma unroll
                for (int r = 0; r < 9; r++) {
                    unsigned m = masks[lane][r];
                    while (m) {
                        int j = r * 32 + __ffs(m) - 1;
                        m &= m - 1;
                        lst[pos++] = (short)j;
                    }
                }
                for (int e = excl + pS; pos < e; pos++)
                    lst[pos] = (short)JS;              // smem zero row
#pragma unroll
                for (int r = 9; r < 16; r++) {
                    unsigned m = masks[lane][r];
                    while (m) {
                        int j = r * 32 + __ffs(m) - 1;
                        m &= m - 1;
                        lst[pos++] = (short)j;
                    }
                }
                for (int e = excl + pt; pos < e; pos++)
                    lst[pos] = (short)CC;              // gmem zero row
            }
            __syncthreads();

            // ---- gather: warp = bucket t, lane = 4 channels.
            //      smem segment (LDS.128) then gmem segment (LDG.128);
            //      ascending-j f32x2 chains + exact zeros -> value-identical. ----
            {
                const int t = warp;
                unsigned long long a01 = 0ull, a23 = 0ull;
                int k = offS_sm[t]; const int eS = offG_sm[t];
#pragma unroll 1
                while (k < eS) {                       // warp-uniform, len % 8 == 0
                    uint4 q = *(const uint4*)(lst + k);
                    ulonglong2 w0 = *(const ulonglong2*)(sWb + (q.x & 0xffffu) * 128);
                    ulonglong2 w1 = *(const ulonglong2*)(sWb + (q.x >> 16)     * 128);
                    ulonglong2 w2 = *(const ulonglong2*)(sWb + (q.y & 0xffffu) * 128);
                    ulonglong2 w3 = *(const ulonglong2*)(sWb + (q.y >> 16)     * 128);
                    ulonglong2 w4 = *(const ulonglong2*)(sWb + (q.z & 0xffffu) * 128);
                    ulonglong2 w5 = *(const ulonglong2*)(sWb + (q.z >> 16)     * 128);
                    ulonglong2 w6 = *(const ulonglong2*)(sWb + (q.w & 0xffffu) * 128);
                    ulonglong2 w7 = *(const ulonglong2*)(sWb + (q.w >> 16)     * 128);
                    ADD_F32X2(a01, a01, w0.x); ADD_F32X2(a23, a23, w0.y);
                    ADD_F32X2(a01, a01, w1.x); ADD_F32X2(a23, a23, w1.y);
                    ADD_F32X2(a01, a01, w2.x); ADD_F32X2(a23, a23, w2.y);
                    ADD_F32X2(a01, a01, w3.x); ADD_F32X2(a23, a23, w3.y);
                    ADD_F32X2(a01, a01, w4.x); ADD_F32X2(a23, a23, w4.y);
                    ADD_F32X2(a01, a01, w5.x); ADD_F32X2(a23, a23, w5.y);
                    ADD_F32X2(a01, a01, w6.x); ADD_F32X2(a23, a23, w6.y);
                    ADD_F32X2(a01, a01, w7.x); ADD_F32X2(a23, a23, w7.y);
                    k += 8;
                }
                k = offG_sm[t]; const int eG = offE_sm[t];
#pragma unroll 1
                while (k < eG) {
                    uint4 q = *(const uint4*)(lst + k);
                    ulonglong2 w0 = *(const ulonglong2*)(Wb + (q.x & 0xffffu) * CC);
                    ulonglong2 w1 = *(const ulonglong2*)(Wb + (q.x >> 16)     * CC);
                    ulonglong2 w2 = *(const ulonglong2*)(Wb + (q.y & 0xffffu) * CC);
                    ulonglong2 w3 = *(const ulonglong2*)(Wb + (q.y >> 16)     * CC);
                    ulonglong2 w4 = *(const ulonglong2*)(Wb + (q.z & 0xffffu) * CC);
                    ulonglong2 w5 = *(const ulonglong2*)(Wb + (q.z >> 16)     * CC);
                    ulonglong2 w6 = *(const ulonglong2*)(Wb + (q.w & 0xffffu) * CC);
                    ulonglong2 w7 = *(const ulonglong2*)(Wb + (q.w >> 16)     * CC);
                    ADD_F32X2(a01, a01, w0.x); ADD_F32X2(a23, a23, w0.y);
                    ADD_F32X2(a01, a01, w1.x); ADD_F32X2(a23, a23, w1.y);
                    ADD_F32X2(a01, a01, w2.x); ADD_F32X2(a23, a23, w2.y);
                    ADD_F32X2(a01, a01, w3.x); ADD_F32X2(a23, a23, w3.y);
                    ADD_F32X2(a01, a01, w4.x); ADD_F32X2(a23, a23, w4.y);
                    ADD_F32X2(a01, a01, w5.x); ADD_F32X2(a23, a23, w5.y);
                    ADD_F32X2(a01, a01, w6.x); ADD_F32X2(a23, a23, w6.y);
                    ADD_F32X2(a01, a01, w7.x); ADD_F32X2(a23, a23, w7.y);
                    k += 8;
                }
                ulonglong2 st; st.x = a01; st.y = a23;
                *(ulonglong2*)(&rec_sm[t][lane * 4]) = st;
            }
            __syncthreads();

            // ---- assemble cur = x + rec (single add, as before) ----
#pragma unroll
            for (int u = 0; u < 4; u++) cur[u] += rec_sm[BASE + u][cl];

            // ---- zeroing / v_init / adaptation (powf values from table) ----
            if (s1_own >= 0) {
#pragma unroll
                for (int u = 0; u < 4; u++)
                    if (BASE + u < s1_own) cur[u] = 0.0f;
            }
            float v_init = (s1_own >= 0) ? 0.0f : mem_last;
            float pw_up  = pw_sm[s1_own + 1][cl];        // p^(s1+1)
            float pw_dn  = pw_sm[TT - 1 - s1_own][cl];   // p^(31-s1)
            float a_at   = pw_up * a_prev + inv_p;
            float new_a  = a_at * pw_dn;
            a_cur  = (s1_own >= 0) ? new_a : pw_sm[TT][cl] * a_prev;
            a_prev = a_cur;
            if (TG == 0) cur[0] += beta * v_init;
        } else {
            a_cur = 0.0f;      // a_kernel0 = 0 -> v_th = 1 exactly
        }

        // ---- publish cur (one STS.128; 16B-aligned, conflict-free) ----
        *(float4*)(crow + BASE) = make_float4(cur[0], cur[1], cur[2], cur[3]);
        __syncthreads();

        // ---- membrane: LDS.128 chunks, per-t ascending-s fmaf chain (exact) ----
        float m[4] = {0.0f, 0.0f, 0.0f, 0.0f};
#pragma unroll
        for (int q = 0; q <= TG; q++) {
            float4 c4 = *(const float4*)(crow + q * 4);
            const float cc4[4] = { c4.x, c4.y, c4.z, c4.w };
#pragma unroll
            for (int w = 0; w < 4; w++) {
                const int s = q * 4 + w;
#pragma unroll
                for (int u = 0; u < 4; u++)
                    if (q < TG || w <= u)
                        m[u] = fmaf(bp[BASE + u - s], cc4[w], m[u]);
            }
        }
        int cand = 64;
#pragma unroll
        for (int u = 0; u < 4; u++) {
            float vth = 1.0f + bb * (ppo[u] * a_cur);
            if (((m[u] - vth) > 0.0f) && cand == 64) cand = BASE + u;
        }
        cand_sm[TG][cl] = cand;
        if (TG == 7) memlast_sm[cl] = m[3];
        __syncthreads();

        // ---- combine: first crossing over all 8 t-groups; mem[31] broadcast ----
        int s1n = min(min(min(cand_sm[0][cl], cand_sm[1][cl]),
                          min(cand_sm[2][cl], cand_sm[3][cl])),
                      min(min(cand_sm[4][cl], cand_sm[5][cl]),
                          min(cand_sm[6][cl], cand_sm[7][cl])));
        int s1_new = (s1n == 64) ? -1 : s1n;
        mem_last = memlast_sm[cl];
        s1_own   = s1_new;

        // ---- write own 4 spikes ----
        {
            float4 v;
            v.x = (BASE + 0 == s1_new) ? 1.0f : 0.0f;
            v.y = (BASE + 1 == s1_new) ? 1.0f : 0.0f;
            v.z = (BASE + 2 == s1_new) ? 1.0f : 0.0f;
            v.w = (BASE + 3 == s1_new) ? 1.0f : 0.0f;
            *(float4*)(orow + iter * TT + BASE) = v;
        }
        if (TG == 0) g_s1buf[iter & 1][b][i] = s1_new;

        // ---- prefetch next x, publish + batch-scope sync ----
        if (iter < NBLK - 1) {
            xv = *(const float4*)(xrow + (iter + 1) * TT + BASE);
            asm volatile("fence.acq_rel.cluster;" ::: "memory");
            asm volatile("barrier.cluster.arrive.aligned;" ::: "memory");
            asm volatile("barrier.cluster.wait.aligned;" ::: "memory");
        }
    }
}

__global__ void __cluster_dims__(4, 1, 1) __launch_bounds__(1024, 1)
snn_kernel(const float* __restrict__ x,
           const float* __restrict__ beta_raw,
           const float* __restrict__ p_raw,
           const float* __restrict__ b_raw,
           float* __restrict__ out)
{
    extern __shared__ __align__(16) float sW[];   // [SW_ROWS][128]

    const int tid  = threadIdx.x;
    const int b    = blockIdx.x >> 2;
    if (b >= BATCH) return;                 // padding clusters exit whole
    const int ctile = blockIdx.x & 3;
    const int cl   = tid & 127;             // channel-local
    const int tg   = tid >> 7;              // t-group (0..7)
    const int lane = tid & 31, warp = tid >> 5;
    const int i    = ctile * 128 + cl;      // channel

    float beta = beta_raw[i];
    beta = fminf(fmaxf(beta, 0.001f), 0.999f);
    float p  = fminf(fabsf(p_raw[i]), 0.999f);
    float bb = fminf(fmaxf(fabsf(b_raw[i]), 0.001f), 1.0f);
    const float inv_p = 1.0f / p;

    __shared__ unsigned            masks[TT][16];
    __shared__ int                 offS_sm[TT], offG_sm[TT], offE_sm[TT];
    __shared__ __align__(16) short lst[1024];
    __shared__ __align__(16) float rec_sm[TT][128];
    __shared__ __align__(16) float cur_sm[128][36];
    __shared__ int                 cand_sm[8][128];
    __shared__ float               memlast_sm[128];
    __shared__ float               pw_sm[TT + 1][128];   // p_cl^k, k=0..32

    // ---- load smem W slice: rows j<JS of this CTA's 128 channels ----
#pragma unroll 1
    for (int k = tid; k < JS * 32; k += 1024) {          // 32 float4 per row
        int j = k >> 5, c4 = k & 31;
        ((float4*)sW)[k] = *(const float4*)(g_WT + (size_t)j * CC + ctile * 128 + c4 * 4);
    }
    if (tid < 32)                                        // zero row JS
        ((float4*)(sW + JS * 128))[tid] = make_float4(0.f, 0.f, 0.f, 0.f);

    // fill per-channel p-power table once (bitwise same powf as before)
#pragma unroll 1
    for (int k = tid; k < (TT + 1) * 128; k += 1024) {
        int ke = k >> 7, c0 = k & 127;
        float pc = fminf(fabsf(p_raw[ctile * 128 + c0]), 0.999f);
        pw_sm[ke][c0] = powf(pc, (float)ke);
    }
    __syncthreads();

    const float* xrow = x   + (size_t)(b * CC + i) * TLEN;
    float*       orow = out + (size_t)(b * CC + i) * TLEN;

    switch (tg) {
    case 0: run_loop<0>(cl, lane, warp, b, i, ctile, xrow, orow, sW, beta, p, bb, inv_p,
                        masks, offS_sm, offG_sm, offE_sm, lst, rec_sm, cur_sm, cand_sm, memlast_sm, pw_sm); break;
    case 1: run_loop<1>(cl, lane, warp, b, i, ctile, xrow, orow, sW, beta, p, bb, inv_p,
                        masks, offS_sm, offG_sm, offE_sm, lst, rec_sm, cur_sm, cand_sm, memlast_sm, pw_sm); break;
    case 2: run_loop<2>(cl, lane, warp, b, i, ctile, xrow, orow, sW, beta, p, bb, inv_p,
                        masks, offS_sm, offG_sm, offE_sm, lst, rec_sm, cur_sm, cand_sm, memlast_sm, pw_sm); break;
    case 3: run_loop<3>(cl, lane, warp, b, i, ctile, xrow, orow, sW, beta, p, bb, inv_p,
                        masks, offS_sm, offG_sm, offE_sm, lst, rec_sm, cur_sm, cand_sm, memlast_sm, pw_sm); break;
    case 4: run_loop<4>(cl, lane, warp, b, i, ctile, xrow, orow, sW, beta, p, bb, inv_p,
                        masks, offS_sm, offG_sm, offE_sm, lst, rec_sm, cur_sm, cand_sm, memlast_sm, pw_sm); break;
    case 5: run_loop<5>(cl, lane, warp, b, i, ctile, xrow, orow, sW, beta, p, bb, inv_p,
                        masks, offS_sm, offG_sm, offE_sm, lst, rec_sm, cur_sm, cand_sm, memlast_sm, pw_sm); break;
    case 6: run_loop<6>(cl, lane, warp, b, i, ctile, xrow, orow, sW, beta, p, bb, inv_p,
                        masks, offS_sm, offG_sm, offE_sm, lst, rec_sm, cur_sm, cand_sm, memlast_sm, pw_sm); break;
    default: run_loop<7>(cl, lane, warp, b, i, ctile, xrow, orow, sW, beta, p, bb, inv_p,
                        masks, offS_sm, offG_sm, offE_sm, lst, rec_sm, cur_sm, cand_sm, memlast_sm, pw_sm); break;
    }
}

// ---------------------------------------------------------------------------
extern "C" void kernel_launch(void* const* d_in, const int* in_sizes, int n_in,
                              void* d_out, int out_size)
{
    const float* x        = (const float*)d_in[0];
    const float* beta_raw = (const float*)d_in[1];
    const float* rec_w    = (const float*)d_in[2];
    const float* p_raw    = (const float*)d_in[3];
    const float* b_raw    = (const float*)d_in[4];
    float* out = (float*)d_out;

    // opt-in to large dynamic smem (host-side attribute, not an allocation)
    static bool attr_set = false;
    if (!attr_set) {
        cudaFuncSetAttribute(snn_kernel,
                             cudaFuncAttributeMaxDynamicSharedMemorySize,
                             SW_BYTES);
        attr_set = true;
    }

    transpose_kernel<<<dim3(16, 16), dim3(32, 8)>>>(rec_w);
    // 148 CTAs (37 clusters of 4): clusters with b>=32 exit immediately
    snn_kernel<<<148, 1024, SW_BYTES>>>(x, beta_raw, p_raw, b_raw, out);
}

// round 9
// speedup vs baseline: 11.9707x; 1.2455x over previous
#include <cuda_runtime.h>
#include <cstdint>

#define CC    512
#define TLEN  1024
#define TT    32
#define NBLK  32
#define BATCH 32
#define JS    320             // j < JS served from smem (NRS mask rounds)
#define NRS   10              // JS / 32
#define SW_ROWS (JS + 1)      // +1 zero row for smem-segment padding
#define SW_BYTES (SW_ROWS * 128 * 4)

// Packed dual-FP32 add (Blackwell f32x2): two independent IEEE adds.
#define ADD_F32X2(out, a, b) \
    asm("add.rn.f32x2 %0, %1, %2;" : "=l"(out) : "l"(a), "l"(b))

// Scratch (no cudaMalloc allowed). Row CC (index 512) of g_WT is NEVER written:
// device globals are zero-initialized -> permanent zero row for gmem padding.
__device__ float g_WT[(CC + 1) * CC];

// ---------------------------------------------------------------------------
// Transpose rec_weight (W[i][j]) -> g_WT[j][i] so the gather is coalesced in i
// ---------------------------------------------------------------------------
__global__ void transpose_kernel(const float* __restrict__ W) {
    __shared__ float tile[32][33];
    int j0 = blockIdx.x * 32, i0 = blockIdx.y * 32;
    int tx = threadIdx.x, ty = threadIdx.y;
#pragma unroll
    for (int k = 0; k < 32; k += 8)
        tile[ty + k][tx] = W[(i0 + ty + k) * CC + (j0 + tx)];
    __syncthreads();
#pragma unroll
    for (int k = 0; k < 32; k += 8)
        g_WT[(j0 + ty + k) * CC + (i0 + tx)] = tile[tx][ty + k];
}

// ---------------------------------------------------------------------------
// R9: DSMEM spike exchange (no gmem round-trip, no explicit fence), parallel
// list extraction, gather fused with x into xs_sm (cur phase + 2 syncs gone),
// membrane applies zero / beta*v_init fixups on the fly (adds exact +-0 ->
// value-identical). JS=320. Bitwise-identical spike decisions.
// ---------------------------------------------------------------------------
template<int TG>
__device__ __forceinline__ void run_loop(
    int cl, int lane, int warp, int b, int i, int ctile,
    const float* __restrict__ xrow, float* __restrict__ orow,
    const float* __restrict__ sW,
    float beta, float p, float bb, float inv_p,
    int       (*s1_sm)[CC],     // [2][512] double-buffered spike times (DSMEM)
    unsigned  (*masks)[16],     // [32][16]
    int* offS_sm, int* offG_sm, int* offE_sm,   // [32] each
    short*     lst,             // [1024] compacted+padded j list
    float     (*xs_sm)[128],    // [32][128] x, then fused x+rec
    int       (*cand_sm)[128],  // [8][128]
    float*     memlast_sm,      // [128]
    float     (*pw_sm)[128],    // [33][128]: p_cl^k
    uint32_t   s1_u32base)      // smem address of s1_sm[0][0]
{
    constexpr int BASE = TG * 4;

    // beta-power table, built exactly like R1-R8 (powf with float exponent)
    float bp[BASE + 4];
#pragma unroll
    for (int k = 0; k < BASE + 4; k++) bp[k] = powf(beta, (float)k);
    float ppo[4];
#pragma unroll
    for (int u = 0; u < 4; u++) ppo[u] = powf(p, (float)(BASE + u + 1));

    float mem_last = 0.0f, a_prev = 0.0f;
    int   s1_own = -1;

    const int tid = TG * 128 + cl;
    const float* Wb  = g_WT + ctile * 128 + lane * 4;  // gmem gather base
    const float* sWb = sW + lane * 4;                  // smem gather base

    // prefetch x block 0
    float4 xv = *(const float4*)(xrow + BASE);

    for (int iter = 0; iter < NBLK; iter++) {
        // ---- phase 1: publish x slice, OR spikes into masks, adaptation ----
        xs_sm[BASE + 0][cl] = xv.x;
        xs_sm[BASE + 1][cl] = xv.y;
        xs_sm[BASE + 2][cl] = xv.z;
        xs_sm[BASE + 3][cl] = xv.w;

        float a_cur, v_init;
        if (iter > 0) {
            const int rb = (iter - 1) & 1;
            if (TG < 4) {
                int s = s1_sm[rb][tid];                // LDS (DSMEM-exchanged)
                if (s >= 0)
                    atomicOr(&masks[s][tid >> 5], 1u << (tid & 31));
            }
            v_init = (s1_own >= 0) ? 0.0f : mem_last;
            float pw_up = pw_sm[s1_own + 1][cl];       // p^(s1+1)
            float pw_dn = pw_sm[TT - 1 - s1_own][cl];  // p^(31-s1)
            float a_at  = pw_up * a_prev + inv_p;
            float new_a = a_at * pw_dn;
            a_cur  = (s1_own >= 0) ? new_a : pw_sm[TT][cl] * a_prev;
            a_prev = a_cur;
        } else {
            a_cur = 0.0f; v_init = 0.0f;               // +0 adds are identity
        }
        __syncthreads();                               // sync 1

        if (iter > 0) {
            // ---- warp 0: counts + scan only (extraction is parallel) ----
            if (TG == 0 && warp == 0) {
                int cntS = 0, cntG = 0;
#pragma unroll
                for (int r = 0; r < NRS; r++)  cntS += __popc(masks[lane][r]);
#pragma unroll
                for (int r = NRS; r < 16; r++) cntG += __popc(masks[lane][r]);
                int pS = (cntS + 7) & ~7;
                int pG = (cntG + 7) & ~7;
                int pt = pS + pG;
                int sc = pt;
#pragma unroll
                for (int d = 1; d < 32; d <<= 1) {
                    int o = __shfl_up_sync(0xffffffffu, sc, d);
                    if (lane >= d) sc += o;
                }
                int excl = sc - pt;
                offS_sm[lane] = excl;
                offG_sm[lane] = excl + pS;
                offE_sm[lane] = excl + pt;
            }
            __syncthreads();                           // sync 2

            // ---- parallel extraction: warp = bucket t, lane = mask round ----
            {
                const int t = warp;
                unsigned mr = (lane < 16) ? masks[t][lane] : 0u;
                int c  = __popc(mr);
                int cS = (lane < NRS) ? c : 0;
                int cG = (lane >= NRS && lane < 16) ? c : 0;
                int sS = cS, sG = cG;
#pragma unroll
                for (int d = 1; d < 32; d <<= 1) {
                    int oS = __shfl_up_sync(0xffffffffu, sS, d);
                    int oG = __shfl_up_sync(0xffffffffu, sG, d);
                    if (lane >= d) { sS += oS; sG += oG; }
                }
                int totS = __shfl_sync(0xffffffffu, sS, 31);
                int totG = __shfl_sync(0xffffffffu, sG, 31);
                int exS = sS - cS, exG = sG - cG;
                int offS = offS_sm[t], offG = offG_sm[t], offE = offE_sm[t];
                int pos = (lane < NRS) ? (offS + exS) : (offG + exG);
                const int jb = lane * 32;
                while (mr) {                           // asc bit within round
                    int j = jb + __ffs(mr) - 1;
                    mr &= mr - 1;
                    lst[pos++] = (short)j;
                }
                int padS = offG - (offS + totS);       // <= 7
                if (lane < padS) lst[offS + totS + lane] = (short)JS;
                int padG = offE - (offG + totG);       // <= 7
                if (lane < padG) lst[offG + totG + lane] = (short)CC;
            }
            __syncthreads();                           // sync 3

            // ---- gather: warp = bucket t, lane = 4 channels; smem then gmem
            //      segment, ascending-j f32x2 chains + exact zeros; finally
            //      fuse x: cur = x + rec (single FADD, commutes bitwise). ----
            {
                const int t = warp;
                unsigned long long a01 = 0ull, a23 = 0ull;
                int k = offS_sm[t]; const int eS = offG_sm[t];
#pragma unroll 1
                while (k < eS) {                       // uniform, len % 8 == 0
                    uint4 q = *(const uint4*)(lst + k);
                    ulonglong2 w0 = *(const ulonglong2*)(sWb + (q.x & 0xffffu) * 128);
                    ulonglong2 w1 = *(const ulonglong2*)(sWb + (q.x >> 16)     * 128);
                    ulonglong2 w2 = *(const ulonglong2*)(sWb + (q.y & 0xffffu) * 128);
                    ulonglong2 w3 = *(const ulonglong2*)(sWb + (q.y >> 16)     * 128);
                    ulonglong2 w4 = *(const ulonglong2*)(sWb + (q.z & 0xffffu) * 128);
                    ulonglong2 w5 = *(const ulonglong2*)(sWb + (q.z >> 16)     * 128);
                    ulonglong2 w6 = *(const ulonglong2*)(sWb + (q.w & 0xffffu) * 128);
                    ulonglong2 w7 = *(const ulonglong2*)(sWb + (q.w >> 16)     * 128);
                    ADD_F32X2(a01, a01, w0.x); ADD_F32X2(a23, a23, w0.y);
                    ADD_F32X2(a01, a01, w1.x); ADD_F32X2(a23, a23, w1.y);
                    ADD_F32X2(a01, a01, w2.x); ADD_F32X2(a23, a23, w2.y);
                    ADD_F32X2(a01, a01, w3.x); ADD_F32X2(a23, a23, w3.y);
                    ADD_F32X2(a01, a01, w4.x); ADD_F32X2(a23, a23, w4.y);
                    ADD_F32X2(a01, a01, w5.x); ADD_F32X2(a23, a23, w5.y);
                    ADD_F32X2(a01, a01, w6.x); ADD_F32X2(a23, a23, w6.y);
                    ADD_F32X2(a01, a01, w7.x); ADD_F32X2(a23, a23, w7.y);
                    k += 8;
                }
                k = offG_sm[t]; const int eG = offE_sm[t];
#pragma unroll 1
                while (k < eG) {
                    uint4 q = *(const uint4*)(lst + k);
                    ulonglong2 w0 = *(const ulonglong2*)(Wb + (q.x & 0xffffu) * CC);
                    ulonglong2 w1 = *(const ulonglong2*)(Wb + (q.x >> 16)     * CC);
                    ulonglong2 w2 = *(const ulonglong2*)(Wb + (q.y & 0xffffu) * CC);
                    ulonglong2 w3 = *(const ulonglong2*)(Wb + (q.y >> 16)     * CC);
                    ulonglong2 w4 = *(const ulonglong2*)(Wb + (q.z & 0xffffu) * CC);
                    ulonglong2 w5 = *(const ulonglong2*)(Wb + (q.z >> 16)     * CC);
                    ulonglong2 w6 = *(const ulonglong2*)(Wb + (q.w & 0xffffu) * CC);
                    ulonglong2 w7 = *(const ulonglong2*)(Wb + (q.w >> 16)     * CC);
                    ADD_F32X2(a01, a01, w0.x); ADD_F32X2(a23, a23, w0.y);
                    ADD_F32X2(a01, a01, w1.x); ADD_F32X2(a23, a23, w1.y);
                    ADD_F32X2(a01, a01, w2.x); ADD_F32X2(a23, a23, w2.y);
                    ADD_F32X2(a01, a01, w3.x); ADD_F32X2(a23, a23, w3.y);
                    ADD_F32X2(a01, a01, w4.x); ADD_F32X2(a23, a23, w4.y);
                    ADD_F32X2(a01, a01, w5.x); ADD_F32X2(a23, a23, w5.y);
                    ADD_F32X2(a01, a01, w6.x); ADD_F32X2(a23, a23, w6.y);
                    ADD_F32X2(a01, a01, w7.x); ADD_F32X2(a23, a23, w7.y);
                    k += 8;
                }
                // cur = x + rec (x first operand, as R8's cur=x; cur+=rec)
                ulonglong2 xv2 = *(const ulonglong2*)(&xs_sm[t][lane * 4]);
                ADD_F32X2(a01, xv2.x, a01);
                ADD_F32X2(a23, xv2.y, a23);
                ulonglong2 st2; st2.x = a01; st2.y = a23;
                *(ulonglong2*)(&xs_sm[t][lane * 4]) = st2;

                // zero masks for the NEXT iteration (read finished at sync 3)
                if (TG >= 4) ((unsigned*)masks)[tid - 512] = 0;
            }
        }
        __syncthreads();                               // sync 4

        // ---- membrane: on-the-fly fixups, exact ascending-s fmaf chains ----
        float m[4] = {0.0f, 0.0f, 0.0f, 0.0f};
        const float bv = beta * v_init;                // +0 when not applicable
#pragma unroll
        for (int s = 0; s < BASE + 4; s++) {
            float val = xs_sm[s][cl];
            if (s < s1_own) val = 0.0f;                // zero before prev spike
            if (s == 0)     val += bv;                 // beta*v_init at t=0
#pragma unroll
            for (int u = 0; u < 4; u++)
                if (s <= BASE + u)
                    m[u] = fmaf(bp[BASE + u - s], val, m[u]);
        }
        int cand = 64;
#pragma unroll
        for (int u = 0; u < 4; u++) {
            float vth = 1.0f + bb * (ppo[u] * a_cur);
            if (((m[u] - vth) > 0.0f) && cand == 64) cand = BASE + u;
        }
        cand_sm[TG][cl] = cand;
        if (TG == 7) memlast_sm[cl] = m[3];
        __syncthreads();                               // sync 5

        // ---- combine: first crossing over all 8 t-groups; mem[31] ----
        int s1n = min(min(min(cand_sm[0][cl], cand_sm[1][cl]),
                          min(cand_sm[2][cl], cand_sm[3][cl])),
                      min(min(cand_sm[4][cl], cand_sm[5][cl]),
                          min(cand_sm[6][cl], cand_sm[7][cl])));
        int s1_new = (s1n == 64) ? -1 : s1n;
        mem_last = memlast_sm[cl];
        s1_own   = s1_new;

        // ---- write own 4 spikes ----
        {
            float4 v;
            v.x = (BASE + 0 == s1_new) ? 1.0f : 0.0f;
            v.y = (BASE + 1 == s1_new) ? 1.0f : 0.0f;
            v.z = (BASE + 2 == s1_new) ? 1.0f : 0.0f;
            v.w = (BASE + 3 == s1_new) ? 1.0f : 0.0f;
            *(float4*)(orow + iter * TT + BASE) = v;
        }

        // ---- DSMEM publish to all 4 CTAs, prefetch next x, cluster barrier
        //      (arrive=release / wait=acquire orders the shared::cluster
        //       stores; no gmem exchange -> no explicit fence needed) ----
        if (iter < NBLK - 1) {
            if (TG == 0) {
                uint32_t loc = s1_u32base +
                               (uint32_t)(((iter & 1) * CC + i) * sizeof(int));
#pragma unroll
                for (int rk = 0; rk < 4; rk++) {
                    uint32_t rem;
                    asm volatile("mapa.shared::cluster.u32 %0, %1, %2;"
                                 : "=r"(rem) : "r"(loc), "r"(rk));
                    asm volatile("st.shared::cluster.u32 [%0], %1;"
                                 :: "r"(rem), "r"(s1_new) : "memory");
                }
            }
            xv = *(const float4*)(xrow + (iter + 1) * TT + BASE);
            asm volatile("barrier.cluster.arrive.aligned;" ::: "memory");
            asm volatile("barrier.cluster.wait.aligned;"   ::: "memory");
        }
    }
}

__global__ void __cluster_dims__(4, 1, 1) __launch_bounds__(1024, 1)
snn_kernel(const float* __restrict__ x,
           const float* __restrict__ beta_raw,
           const float* __restrict__ p_raw,
           const float* __restrict__ b_raw,
           float* __restrict__ out)
{
    extern __shared__ __align__(16) float sW[];   // [SW_ROWS][128]

    const int tid  = threadIdx.x;
    const int b    = blockIdx.x >> 2;
    if (b >= BATCH) return;                 // padding clusters exit whole
    const int ctile = blockIdx.x & 3;
    const int cl   = tid & 127;             // channel-local
    const int tg   = tid >> 7;              // t-group (0..7)
    const int lane = tid & 31, warp = tid >> 5;
    const int i    = ctile * 128 + cl;      // channel

    float beta = beta_raw[i];
    beta = fminf(fmaxf(beta, 0.001f), 0.999f);
    float p  = fminf(fabsf(p_raw[i]), 0.999f);
    float bb = fminf(fmaxf(fabsf(b_raw[i]), 0.001f), 1.0f);
    const float inv_p = 1.0f / p;

    __shared__ int                 s1_sm[2][CC];
    __shared__ unsigned            masks[TT][16];
    __shared__ int                 offS_sm[TT], offG_sm[TT], offE_sm[TT];
    __shared__ __align__(16) short lst[1024];
    __shared__ __align__(16) float xs_sm[TT][128];
    __shared__ int                 cand_sm[8][128];
    __shared__ float               memlast_sm[128];
    __shared__ float               pw_sm[TT + 1][128];   // p_cl^k, k=0..32

    uint32_t s1_u32base;
    asm("{ .reg .u64 t0; cvta.to.shared.u64 t0, %1; cvt.u32.u64 %0, t0; }"
        : "=r"(s1_u32base) : "l"(&s1_sm[0][0]));

    // ---- init: smem W slice (rows j<JS), zero row, masks zero, pw table ----
#pragma unroll 1
    for (int k = tid; k < JS * 32; k += 1024) {          // 32 float4 per row
        int j = k >> 5, c4 = k & 31;
        ((float4*)sW)[k] = *(const float4*)(g_WT + (size_t)j * CC + ctile * 128 + c4 * 4);
    }
    if (tid < 32)                                        // zero row JS
        ((float4*)(sW + JS * 128))[tid] = make_float4(0.f, 0.f, 0.f, 0.f);
    if (tid < TT * 16)
        ((unsigned*)masks)[tid] = 0;                     // first-use zeroing
#pragma unroll 1
    for (int k = tid; k < (TT + 1) * 128; k += 1024) {
        int ke = k >> 7, c0 = k & 127;
        float pc = fminf(fabsf(p_raw[ctile * 128 + c0]), 0.999f);
        pw_sm[ke][c0] = powf(pc, (float)ke);
    }
    __syncthreads();

    const float* xrow = x   + (size_t)(b * CC + i) * TLEN;
    float*       orow = out + (size_t)(b * CC + i) * TLEN;

    switch (tg) {
    case 0: run_loop<0>(cl, lane, warp, b, i, ctile, xrow, orow, sW, beta, p, bb, inv_p,
                        s1_sm, masks, offS_sm, offG_sm, offE_sm, lst, xs_sm, cand_sm, memlast_sm, pw_sm, s1_u32base); break;
    case 1: run_loop<1>(cl, lane, warp, b, i, ctile, xrow, orow, sW, beta, p, bb, inv_p,
                        s1_sm, masks, offS_sm, offG_sm, offE_sm, lst, xs_sm, cand_sm, memlast_sm, pw_sm, s1_u32base); break;
    case 2: run_loop<2>(cl, lane, warp, b, i, ctile, xrow, orow, sW, beta, p, bb, inv_p,
                        s1_sm, masks, offS_sm, offG_sm, offE_sm, lst, xs_sm, cand_sm, memlast_sm, pw_sm, s1_u32base); break;
    case 3: run_loop<3>(cl, lane, warp, b, i, ctile, xrow, orow, sW, beta, p, bb, inv_p,
                        s1_sm, masks, offS_sm, offG_sm, offE_sm, lst, xs_sm, cand_sm, memlast_sm, pw_sm, s1_u32base); break;
    case 4: run_loop<4>(cl, lane, warp, b, i, ctile, xrow, orow, sW, beta, p, bb, inv_p,
                        s1_sm, masks, offS_sm, offG_sm, offE_sm, lst, xs_sm, cand_sm, memlast_sm, pw_sm, s1_u32base); break;
    case 5: run_loop<5>(cl, lane, warp, b, i, ctile, xrow, orow, sW, beta, p, bb, inv_p,
                        s1_sm, masks, offS_sm, offG_sm, offE_sm, lst, xs_sm, cand_sm, memlast_sm, pw_sm, s1_u32base); break;
    case 6: run_loop<6>(cl, lane, warp, b, i, ctile, xrow, orow, sW, beta, p, bb, inv_p,
                        s1_sm, masks, offS_sm, offG_sm, offE_sm, lst, xs_sm, cand_sm, memlast_sm, pw_sm, s1_u32base); break;
    default: run_loop<7>(cl, lane, warp, b, i, ctile, xrow, orow, sW, beta, p, bb, inv_p,
                        s1_sm, masks, offS_sm, offG_sm, offE_sm, lst, xs_sm, cand_sm, memlast_sm, pw_sm, s1_u32base); break;
    }
}

// ---------------------------------------------------------------------------
extern "C" void kernel_launch(void* const* d_in, const int* in_sizes, int n_in,
                              void* d_out, int out_size)
{
    const float* x        = (const float*)d_in[0];
    const float* beta_raw = (const float*)d_in[1];
    const float* rec_w    = (const float*)d_in[2];
    const float* p_raw    = (const float*)d_in[3];
    const float* b_raw    = (const float*)d_in[4];
    float* out = (float*)d_out;

    // opt-in to large dynamic smem (host-side attribute, not an allocation)
    static bool attr_set = false;
    if (!attr_set) {
        cudaFuncSetAttribute(snn_kernel,
                             cudaFuncAttributeMaxDynamicSharedMemorySize,
                             SW_BYTES);
        attr_set = true;
    }

    transpose_kernel<<<dim3(16, 16), dim3(32, 8)>>>(rec_w);
    // 148 CTAs (37 clusters of 4): clusters with b>=32 exit immediately
    snn_kernel<<<148, 1024, SW_BYTES>>>(x, beta_raw, p_raw, b_raw, out);
}